// round 1
// baseline (speedup 1.0000x reference)
#include <cuda_runtime.h>

// ---------------- problem constants ----------------
#define B_   8
#define C_   512
#define HH_  32
#define WW_  32
#define L_   1024          // HH*WW
#define NH_  4
#define D_   128
#define KC_  4608          // 512*9 (im2col K)
#define QSCALE 0.08838834764831845f  // 128^-0.5

// ---------------- scratch (device globals; no allocations) ----------------
__device__ float g_y1[B_*C_*L_];            // relu(bn1(x))        16MB
__device__ float g_q [B_*NH_*L_*D_];        // scaled q            16MB
__device__ float g_k [B_*NH_*L_*D_];        //                     16MB
__device__ float g_v [B_*NH_*L_*D_];        //                     16MB
__device__ float g_rdot[B_*NH_*L_*128];     // rel dots (126 used) 16MB
__device__ float g_logits[(size_t)B_*NH_*L_*L_]; // attn logits   134MB
__device__ float g_xres[B_*C_*L_];          // mhsa out + x        16MB
__device__ float g_y2[B_*C_*L_];            // relu(bn2(xres))     16MB
__device__ float g_col[(size_t)B_*KC_*L_];  // im2col             151MB

// ---------------- elementwise: BN + ReLU ----------------
__global__ void bn_relu1_kernel(const float* __restrict__ x,
                                const float* __restrict__ g, const float* __restrict__ bb,
                                const float* __restrict__ m, const float* __restrict__ v) {
    int idx = blockIdx.x * 256 + threadIdx.x;
    int c = (idx >> 10) & (C_ - 1);
    float inv = g[c] * rsqrtf(v[c] + 1e-5f);
    float val = fmaf(x[idx], inv, bb[c] - m[c] * inv);
    g_y1[idx] = fmaxf(val, 0.0f);
}

__global__ void bn_relu2_kernel(const float* __restrict__ g, const float* __restrict__ bb,
                                const float* __restrict__ m, const float* __restrict__ v) {
    int idx = blockIdx.x * 256 + threadIdx.x;
    int c = (idx >> 10) & (C_ - 1);
    float inv = g[c] * rsqrtf(v[c] + 1e-5f);
    float val = fmaf(g_xres[idx], inv, bb[c] - m[c] * inv);
    g_y2[idx] = fmaxf(val, 0.0f);
}

// ---------------- QKV projection GEMM ----------------
// Per batch b: C[l, o] = sum_c y1[b,c,l] * W[o,c];  O = 1536 (q|k|v), K = 512
// grid (12, 8, 8) : (o-tile, l-tile, batch). 256 threads, 8x8 per thread.
__global__ __launch_bounds__(256) void proj_kernel(const float* __restrict__ w_qk,
                                                   const float* __restrict__ w_v) {
    __shared__ float As[16][128];
    __shared__ float Bs[16][128];
    const int b  = blockIdx.z;
    const int m0 = blockIdx.y * 128;         // l
    const int nt = blockIdx.x;               // o-tile 0..11
    const int n0 = nt * 128;
    const int tid = threadIdx.x;
    const int tx = tid & 15, ty = tid >> 4;

    const float* A = g_y1 + (size_t)b * (C_ * L_);   // A[k=c][m=l], row stride L_
    const float* Wb; int nbase;
    if (nt < 8) { Wb = w_qk; nbase = n0; } else { Wb = w_v; nbase = n0 - 1024; }

    float acc[8][8];
    #pragma unroll
    for (int i = 0; i < 8; i++)
        #pragma unroll
        for (int j = 0; j < 8; j++) acc[i][j] = 0.f;

    for (int k0 = 0; k0 < 512; k0 += 16) {
        #pragma unroll
        for (int e = 0; e < 2; e++) {                 // A: m-contiguous
            int li = tid + e * 256;
            int mm = (li & 31) << 2;
            int kk = li >> 5;
            *(float4*)&As[kk][mm] =
                *(const float4*)(A + (size_t)(k0 + kk) * L_ + m0 + mm);
        }
        #pragma unroll
        for (int e = 0; e < 2; e++) {                 // B: k-contiguous (W row-major)
            int li = tid + e * 256;
            int k4 = (li & 3) << 2;
            int nn = li >> 2;
            float4 f = *(const float4*)(Wb + (size_t)(nbase + nn) * 512 + k0 + k4);
            Bs[k4+0][nn] = f.x; Bs[k4+1][nn] = f.y; Bs[k4+2][nn] = f.z; Bs[k4+3][nn] = f.w;
        }
        __syncthreads();
        #pragma unroll
        for (int kk = 0; kk < 16; kk++) {
            float a[8], br[8];
            #pragma unroll
            for (int i = 0; i < 8; i++) a[i]  = As[kk][ty * 8 + i];
            #pragma unroll
            for (int j = 0; j < 8; j++) br[j] = Bs[kk][tx * 8 + j];
            #pragma unroll
            for (int i = 0; i < 8; i++)
                #pragma unroll
                for (int j = 0; j < 8; j++) acc[i][j] = fmaf(a[i], br[j], acc[i][j]);
        }
        __syncthreads();
    }

    float* dst; float scale = 1.0f; int head;
    if (nt < 4)      { dst = g_q; head = nt;     scale = QSCALE; }
    else if (nt < 8) { dst = g_k; head = nt - 4; }
    else             { dst = g_v; head = nt - 8; }
    size_t base = (size_t)(b * NH_ + head) * L_ * D_;
    #pragma unroll
    for (int i = 0; i < 8; i++) {
        int mrow = m0 + ty * 8 + i;
        float* o = dst + base + (size_t)mrow * D_ + tx * 8;
        #pragma unroll
        for (int j = 0; j < 8; j++) o[j] = acc[i][j] * scale;
    }
}

// ---------------- relative position dots ----------------
// rdot[row, r] = q[row,:]·rel_w[r]   (r<63), = q[row,:]·rel_h[r-63] (63<=r<126)
__global__ void relpos_kernel(const float* __restrict__ rel_h,
                              const float* __restrict__ rel_w) {
    __shared__ float qs[128];
    const int row = blockIdx.x;            // 0..32767  ( (b*4+n)*1024 + l )
    const int tid = threadIdx.x;           // 128
    qs[tid] = g_q[(size_t)row * D_ + tid];
    __syncthreads();
    if (tid < 126) {
        const float* rk = (tid < 63) ? (rel_w + tid * D_) : (rel_h + (tid - 63) * D_);
        float s0 = 0.f, s1 = 0.f;
        #pragma unroll 16
        for (int d = 0; d < 128; d += 2) {
            s0 = fmaf(qs[d],     rk[d],     s0);
            s1 = fmaf(qs[d + 1], rk[d + 1], s1);
        }
        g_rdot[(size_t)row * 128 + tid] = s0 + s1;
    }
}

// ---------------- logits = Q Kᵀ + pos_bias ----------------
// grid (8, 8, 32): (j-tile, i-tile, b*4+n). K = 128.
__global__ __launch_bounds__(256) void logits_kernel() {
    __shared__ float As[16][128];
    __shared__ float Bs[16][128];
    const int bn = blockIdx.z;
    const int m0 = blockIdx.y * 128;       // i
    const int n0 = blockIdx.x * 128;       // j
    const int tid = threadIdx.x;
    const int tx = tid & 15, ty = tid >> 4;
    const float* A  = g_q + (size_t)bn * L_ * D_;
    const float* Bk = g_k + (size_t)bn * L_ * D_;

    float acc[8][8];
    #pragma unroll
    for (int i = 0; i < 8; i++)
        #pragma unroll
        for (int j = 0; j < 8; j++) acc[i][j] = 0.f;

    for (int k0 = 0; k0 < 128; k0 += 16) {
        #pragma unroll
        for (int e = 0; e < 2; e++) {                 // both k-contiguous
            int li = tid + e * 256;
            int k4 = (li & 3) << 2;
            int mm = li >> 2;
            float4 f = *(const float4*)(A + (size_t)(m0 + mm) * D_ + k0 + k4);
            As[k4+0][mm] = f.x; As[k4+1][mm] = f.y; As[k4+2][mm] = f.z; As[k4+3][mm] = f.w;
            float4 g4 = *(const float4*)(Bk + (size_t)(n0 + mm) * D_ + k0 + k4);
            Bs[k4+0][mm] = g4.x; Bs[k4+1][mm] = g4.y; Bs[k4+2][mm] = g4.z; Bs[k4+3][mm] = g4.w;
        }
        __syncthreads();
        #pragma unroll
        for (int kk = 0; kk < 16; kk++) {
            float a[8], br[8];
            #pragma unroll
            for (int i = 0; i < 8; i++) a[i]  = As[kk][ty * 8 + i];
            #pragma unroll
            for (int j = 0; j < 8; j++) br[j] = Bs[kk][tx * 8 + j];
            #pragma unroll
            for (int i = 0; i < 8; i++)
                #pragma unroll
                for (int j = 0; j < 8; j++) acc[i][j] = fmaf(a[i], br[j], acc[i][j]);
        }
        __syncthreads();
    }

    const float* rd = g_rdot + (size_t)bn * L_ * 128;
    float* out = g_logits + (size_t)bn * L_ * L_;
    #pragma unroll
    for (int i = 0; i < 8; i++) {
        int ii = m0 + ty * 8 + i;
        int h = ii >> 5, w = ii & 31;
        const float* rrow = rd + (size_t)ii * 128;
        #pragma unroll
        for (int j = 0; j < 8; j++) {
            int jj = n0 + tx * 8 + j;
            int h2 = jj >> 5, w2 = jj & 31;
            float bias = rrow[w2 - w + 31] + rrow[63 + h2 - h + 31];
            out[(size_t)ii * L_ + jj] = acc[i][j] + bias;
        }
    }
}

// ---------------- softmax over rows of 1024 (in place) ----------------
__global__ void softmax_kernel() {
    const int row = blockIdx.x;            // 32768
    float* p = g_logits + (size_t)row * L_;
    const int tid = threadIdx.x;           // 256
    float4 v4 = *(float4*)(p + tid * 4);
    float mx = fmaxf(fmaxf(v4.x, v4.y), fmaxf(v4.z, v4.w));
    __shared__ float smax[8], ssum[8];
    #pragma unroll
    for (int o = 16; o; o >>= 1) mx = fmaxf(mx, __shfl_xor_sync(~0u, mx, o));
    if ((tid & 31) == 0) smax[tid >> 5] = mx;
    __syncthreads();
    if (tid == 0) {
        float t = smax[0];
        #pragma unroll
        for (int i = 1; i < 8; i++) t = fmaxf(t, smax[i]);
        smax[0] = t;
    }
    __syncthreads();
    mx = smax[0];
    float e0 = __expf(v4.x - mx), e1 = __expf(v4.y - mx);
    float e2 = __expf(v4.z - mx), e3 = __expf(v4.w - mx);
    float s = (e0 + e1) + (e2 + e3);
    #pragma unroll
    for (int o = 16; o; o >>= 1) s += __shfl_xor_sync(~0u, s, o);
    if ((tid & 31) == 0) ssum[tid >> 5] = s;
    __syncthreads();
    if (tid == 0) {
        float t = 0.f;
        #pragma unroll
        for (int i = 0; i < 8; i++) t += ssum[i];
        ssum[0] = t;
    }
    __syncthreads();
    float inv = 1.0f / ssum[0];
    float4 r = make_float4(e0 * inv, e1 * inv, e2 * inv, e3 * inv);
    *(float4*)(p + tid * 4) = r;
}

// ---------------- AV GEMM + head merge + residual ----------------
// grid (1, 8, 32): C[i,d] = sum_j attn[i,j] v[j,d];  write xres[(b,c=n*128+d),i] = C + x
__global__ __launch_bounds__(256) void av_kernel(const float* __restrict__ x) {
    __shared__ float As[16][128];
    __shared__ float Bs[16][128];
    const int bn = blockIdx.z;
    const int b = bn >> 2, nh = bn & 3;
    const int m0 = blockIdx.y * 128;       // i
    const int tid = threadIdx.x;
    const int tx = tid & 15, ty = tid >> 4;
    const float* A  = g_logits + (size_t)bn * L_ * L_;   // [i][j], k-contig
    const float* Bv = g_v      + (size_t)bn * L_ * D_;   // [j][d], n-contig

    float acc[8][8];
    #pragma unroll
    for (int i = 0; i < 8; i++)
        #pragma unroll
        for (int j = 0; j < 8; j++) acc[i][j] = 0.f;

    for (int k0 = 0; k0 < L_; k0 += 16) {
        #pragma unroll
        for (int e = 0; e < 2; e++) {                 // A: k-contiguous
            int li = tid + e * 256;
            int k4 = (li & 3) << 2;
            int mm = li >> 2;
            float4 f = *(const float4*)(A + (size_t)(m0 + mm) * L_ + k0 + k4);
            As[k4+0][mm] = f.x; As[k4+1][mm] = f.y; As[k4+2][mm] = f.z; As[k4+3][mm] = f.w;
        }
        #pragma unroll
        for (int e = 0; e < 2; e++) {                 // B: n-contiguous
            int li = tid + e * 256;
            int nn = (li & 31) << 2;
            int kk = li >> 5;
            *(float4*)&Bs[kk][nn] = *(const float4*)(Bv + (size_t)(k0 + kk) * D_ + nn);
        }
        __syncthreads();
        #pragma unroll
        for (int kk = 0; kk < 16; kk++) {
            float a[8], br[8];
            #pragma unroll
            for (int i = 0; i < 8; i++) a[i]  = As[kk][ty * 8 + i];
            #pragma unroll
            for (int j = 0; j < 8; j++) br[j] = Bs[kk][tx * 8 + j];
            #pragma unroll
            for (int i = 0; i < 8; i++)
                #pragma unroll
                for (int j = 0; j < 8; j++) acc[i][j] = fmaf(a[i], br[j], acc[i][j]);
        }
        __syncthreads();
    }
    #pragma unroll
    for (int i = 0; i < 8; i++) {
        int ii = m0 + ty * 8 + i;
        #pragma unroll
        for (int j = 0; j < 8; j++) {
            int d = tx * 8 + j;
            size_t idx = (size_t)(b * C_ + nh * D_ + d) * L_ + ii;
            g_xres[idx] = acc[i][j] + x[idx];
        }
    }
}

// ---------------- im2col (3x3, pad 1) ----------------
__global__ void im2col_kernel() {
    int idx = blockIdx.x * 256 + threadIdx.x;      // < 8*4608*1024
    int l  = idx & (L_ - 1);
    int kk = (idx >> 10) % KC_;
    int b  = idx / (KC_ * L_);
    int c  = kk / 9, r9 = kk % 9;
    int kh = r9 / 3, kw = r9 % 3;
    int h = (l >> 5) + kh - 1, w = (l & 31) + kw - 1;
    float val = 0.f;
    if (h >= 0 && h < HH_ && w >= 0 && w < WW_)
        val = g_y2[(size_t)(b * C_ + c) * L_ + (h << 5) + w];
    g_col[idx] = val;
}

// ---------------- conv GEMM + bias + residual -> d_out ----------------
// grid (8, 4, 8): C[o,l] = sum_k Wf[o,k] col[b,k,l];  K = 4608
__global__ __launch_bounds__(256) void conv_kernel(const float* __restrict__ w_fc,
                                                   const float* __restrict__ bias_fc,
                                                   float* __restrict__ out) {
    __shared__ float As[16][128];
    __shared__ float Bs[16][128];
    const int b  = blockIdx.z;
    const int m0 = blockIdx.y * 128;       // o
    const int n0 = blockIdx.x * 128;       // l
    const int tid = threadIdx.x;
    const int tx = tid & 15, ty = tid >> 4;
    const float* A  = w_fc;                             // [o][k], k-contig, ld=4608
    const float* Bc = g_col + (size_t)b * KC_ * L_;     // [k][l], n-contig

    float acc[8][8];
    #pragma unroll
    for (int i = 0; i < 8; i++)
        #pragma unroll
        for (int j = 0; j < 8; j++) acc[i][j] = 0.f;

    for (int k0 = 0; k0 < KC_; k0 += 16) {
        #pragma unroll
        for (int e = 0; e < 2; e++) {                 // A: k-contiguous
            int li = tid + e * 256;
            int k4 = (li & 3) << 2;
            int mm = li >> 2;
            float4 f = *(const float4*)(A + (size_t)(m0 + mm) * KC_ + k0 + k4);
            As[k4+0][mm] = f.x; As[k4+1][mm] = f.y; As[k4+2][mm] = f.z; As[k4+3][mm] = f.w;
        }
        #pragma unroll
        for (int e = 0; e < 2; e++) {                 // B: n-contiguous
            int li = tid + e * 256;
            int nn = (li & 31) << 2;
            int kk = li >> 5;
            *(float4*)&Bs[kk][nn] = *(const float4*)(Bc + (size_t)(k0 + kk) * L_ + n0 + nn);
        }
        __syncthreads();
        #pragma unroll
        for (int kk = 0; kk < 16; kk++) {
            float a[8], br[8];
            #pragma unroll
            for (int i = 0; i < 8; i++) a[i]  = As[kk][ty * 8 + i];
            #pragma unroll
            for (int j = 0; j < 8; j++) br[j] = Bs[kk][tx * 8 + j];
            #pragma unroll
            for (int i = 0; i < 8; i++)
                #pragma unroll
                for (int j = 0; j < 8; j++) acc[i][j] = fmaf(a[i], br[j], acc[i][j]);
        }
        __syncthreads();
    }
    #pragma unroll
    for (int i = 0; i < 8; i++) {
        int oo = m0 + ty * 8 + i;
        float bv = bias_fc[oo];
        size_t rowbase = (size_t)(b * C_ + oo) * L_ + n0 + tx * 8;
        #pragma unroll
        for (int j = 0; j < 8; j++)
            out[rowbase + j] = acc[i][j] + bv + g_xres[rowbase + j];
    }
}

// ---------------- launch ----------------
extern "C" void kernel_launch(void* const* d_in, const int* in_sizes, int n_in,
                              void* d_out, int out_size) {
    const float* x       = (const float*)d_in[0];
    const float* w_qk    = (const float*)d_in[1];
    const float* w_v     = (const float*)d_in[2];
    const float* rel_h   = (const float*)d_in[3];
    const float* rel_w   = (const float*)d_in[4];
    const float* g1      = (const float*)d_in[5];
    const float* b1      = (const float*)d_in[6];
    const float* m1      = (const float*)d_in[7];
    const float* v1      = (const float*)d_in[8];
    const float* g2      = (const float*)d_in[9];
    const float* b2      = (const float*)d_in[10];
    const float* m2      = (const float*)d_in[11];
    const float* v2      = (const float*)d_in[12];
    const float* w_fc    = (const float*)d_in[13];
    const float* bias_fc = (const float*)d_in[14];
    float* out = (float*)d_out;

    bn_relu1_kernel<<<(B_*C_*L_)/256, 256>>>(x, g1, b1, m1, v1);
    proj_kernel<<<dim3(12, 8, B_), 256>>>(w_qk, w_v);
    relpos_kernel<<<B_*NH_*L_, 128>>>(rel_h, rel_w);
    logits_kernel<<<dim3(8, 8, B_*NH_), 256>>>();
    softmax_kernel<<<B_*NH_*L_, 256>>>();
    av_kernel<<<dim3(1, 8, B_*NH_), 256>>>(x);
    bn_relu2_kernel<<<(B_*C_*L_)/256, 256>>>(g2, b2, m2, v2);
    im2col_kernel<<<(B_*KC_*L_)/256, 256>>>();
    conv_kernel<<<dim3(8, 4, B_), 256>>>(w_fc, bias_fc, out);
}

// round 3
// speedup vs baseline: 1.2083x; 1.2083x over previous
#include <cuda_runtime.h>
#include <cuda_bf16.h>
#include <cstdint>

// ---------------- problem constants ----------------
#define B_   8
#define C_   512
#define HH_  32
#define WW_  32
#define L_   1024          // HH*WW
#define NH_  4
#define D_   128
#define KC_  4608          // 512*9 (im2col K)
#define QSCALE 0.08838834764831845f  // 128^-0.5

// ---------------- scratch (device globals; no allocations) ----------------
__device__ float g_y1[B_*C_*L_];            // relu(bn1(x))
__device__ float g_q [B_*NH_*L_*D_];        // scaled q
__device__ float g_k [B_*NH_*L_*D_];
__device__ float g_v [B_*NH_*L_*D_];
__device__ float g_rdot[B_*NH_*L_*128];     // rel dots (126 used)
__device__ float g_logits[(size_t)B_*NH_*L_*L_]; // attn logits
__device__ float g_xres[B_*C_*L_];          // mhsa out + x
__device__ float g_y2[B_*C_*L_];            // relu(bn2(xres))
__device__ __nv_bfloat16 g_w_hi[(size_t)C_*KC_];
__device__ __nv_bfloat16 g_w_lo[(size_t)C_*KC_];
__device__ __nv_bfloat16 g_col_hi[(size_t)B_*L_*KC_];  // [b][l][k], k contiguous
__device__ __nv_bfloat16 g_col_lo[(size_t)B_*L_*KC_];

// ================= mma.sync helpers =================
__device__ __forceinline__ uint32_t smem_u32(const void* p) {
    uint32_t a;
    asm("{ .reg .u64 t; cvta.to.shared.u64 t, %1; cvt.u32.u64 %0, t; }" : "=r"(a) : "l"(p));
    return a;
}
__device__ __forceinline__ void cp16(uint32_t s, const void* g) {
    asm volatile("cp.async.cg.shared.global [%0], [%1], 16;" :: "r"(s), "l"(g));
}
#define CP_COMMIT() asm volatile("cp.async.commit_group;" ::: "memory")
#define CP_WAIT(n)  asm volatile("cp.async.wait_group %0;" :: "n"(n) : "memory")

__device__ __forceinline__ void ldmx4(uint32_t* d, uint32_t addr) {
    asm volatile("ldmatrix.sync.aligned.m8n8.x4.shared.b16 {%0,%1,%2,%3}, [%4];"
                 : "=r"(d[0]), "=r"(d[1]), "=r"(d[2]), "=r"(d[3]) : "r"(addr));
}
__device__ __forceinline__ void mma16816(float* c, const uint32_t* a, uint32_t b0, uint32_t b1) {
    asm volatile("mma.sync.aligned.m16n8k16.row.col.f32.bf16.bf16.f32 "
                 "{%0,%1,%2,%3}, {%4,%5,%6,%7}, {%8,%9}, {%0,%1,%2,%3};"
                 : "+f"(c[0]), "+f"(c[1]), "+f"(c[2]), "+f"(c[3])
                 : "r"(a[0]), "r"(a[1]), "r"(a[2]), "r"(a[3]), "r"(b0), "r"(b1));
}
#define SWZ(x) ((x) ^ (((x) >> 3) & 0x70))

// ---------------- elementwise: BN + ReLU ----------------
__global__ void bn_relu1_kernel(const float* __restrict__ x,
                                const float* __restrict__ g, const float* __restrict__ bb,
                                const float* __restrict__ m, const float* __restrict__ v) {
    int idx = blockIdx.x * 256 + threadIdx.x;
    int c = (idx >> 10) & (C_ - 1);
    float inv = g[c] * rsqrtf(v[c] + 1e-5f);
    float val = fmaf(x[idx], inv, bb[c] - m[c] * inv);
    g_y1[idx] = fmaxf(val, 0.0f);
}

__global__ void bn_relu2_kernel(const float* __restrict__ g, const float* __restrict__ bb,
                                const float* __restrict__ m, const float* __restrict__ v) {
    int idx = blockIdx.x * 256 + threadIdx.x;
    int c = (idx >> 10) & (C_ - 1);
    float inv = g[c] * rsqrtf(v[c] + 1e-5f);
    float val = fmaf(g_xres[idx], inv, bb[c] - m[c] * inv);
    g_y2[idx] = fmaxf(val, 0.0f);
}

// ---------------- QKV projection GEMM (fp32 SIMT) ----------------
__global__ __launch_bounds__(256) void proj_kernel(const float* __restrict__ w_qk,
                                                   const float* __restrict__ w_v) {
    __shared__ float As[16][128];
    __shared__ float Bs[16][128];
    const int b  = blockIdx.z;
    const int m0 = blockIdx.y * 128;
    const int nt = blockIdx.x;
    const int n0 = nt * 128;
    const int tid = threadIdx.x;
    const int tx = tid & 15, ty = tid >> 4;

    const float* A = g_y1 + (size_t)b * (C_ * L_);
    const float* Wb; int nbase;
    if (nt < 8) { Wb = w_qk; nbase = n0; } else { Wb = w_v; nbase = n0 - 1024; }

    float acc[8][8];
    #pragma unroll
    for (int i = 0; i < 8; i++)
        #pragma unroll
        for (int j = 0; j < 8; j++) acc[i][j] = 0.f;

    for (int k0 = 0; k0 < 512; k0 += 16) {
        #pragma unroll
        for (int e = 0; e < 2; e++) {
            int li = tid + e * 256;
            int mm = (li & 31) << 2;
            int kk = li >> 5;
            *(float4*)&As[kk][mm] =
                *(const float4*)(A + (size_t)(k0 + kk) * L_ + m0 + mm);
        }
        #pragma unroll
        for (int e = 0; e < 2; e++) {
            int li = tid + e * 256;
            int k4 = (li & 3) << 2;
            int nn = li >> 2;
            float4 f = *(const float4*)(Wb + (size_t)(nbase + nn) * 512 + k0 + k4);
            Bs[k4+0][nn] = f.x; Bs[k4+1][nn] = f.y; Bs[k4+2][nn] = f.z; Bs[k4+3][nn] = f.w;
        }
        __syncthreads();
        #pragma unroll
        for (int kk = 0; kk < 16; kk++) {
            float a[8], br[8];
            #pragma unroll
            for (int i = 0; i < 8; i++) a[i]  = As[kk][ty * 8 + i];
            #pragma unroll
            for (int j = 0; j < 8; j++) br[j] = Bs[kk][tx * 8 + j];
            #pragma unroll
            for (int i = 0; i < 8; i++)
                #pragma unroll
                for (int j = 0; j < 8; j++) acc[i][j] = fmaf(a[i], br[j], acc[i][j]);
        }
        __syncthreads();
    }

    float* dst; float scale = 1.0f; int head;
    if (nt < 4)      { dst = g_q; head = nt;     scale = QSCALE; }
    else if (nt < 8) { dst = g_k; head = nt - 4; }
    else             { dst = g_v; head = nt - 8; }
    size_t base = (size_t)(b * NH_ + head) * L_ * D_;
    #pragma unroll
    for (int i = 0; i < 8; i++) {
        int mrow = m0 + ty * 8 + i;
        float* o = dst + base + (size_t)mrow * D_ + tx * 8;
        #pragma unroll
        for (int j = 0; j < 8; j++) o[j] = acc[i][j] * scale;
    }
}

// ---------------- relative position dots ----------------
__global__ void relpos_kernel(const float* __restrict__ rel_h,
                              const float* __restrict__ rel_w) {
    __shared__ float qs[128];
    const int row = blockIdx.x;
    const int tid = threadIdx.x;
    qs[tid] = g_q[(size_t)row * D_ + tid];
    __syncthreads();
    if (tid < 126) {
        const float* rk = (tid < 63) ? (rel_w + tid * D_) : (rel_h + (tid - 63) * D_);
        float s0 = 0.f, s1 = 0.f;
        #pragma unroll 16
        for (int d = 0; d < 128; d += 2) {
            s0 = fmaf(qs[d],     rk[d],     s0);
            s1 = fmaf(qs[d + 1], rk[d + 1], s1);
        }
        g_rdot[(size_t)row * 128 + tid] = s0 + s1;
    }
}

// ---------------- logits = Q Kᵀ + pos_bias ----------------
__global__ __launch_bounds__(256) void logits_kernel() {
    __shared__ float As[16][128];
    __shared__ float Bs[16][128];
    const int bn = blockIdx.z;
    const int m0 = blockIdx.y * 128;
    const int n0 = blockIdx.x * 128;
    const int tid = threadIdx.x;
    const int tx = tid & 15, ty = tid >> 4;
    const float* A  = g_q + (size_t)bn * L_ * D_;
    const float* Bk = g_k + (size_t)bn * L_ * D_;

    float acc[8][8];
    #pragma unroll
    for (int i = 0; i < 8; i++)
        #pragma unroll
        for (int j = 0; j < 8; j++) acc[i][j] = 0.f;

    for (int k0 = 0; k0 < 128; k0 += 16) {
        #pragma unroll
        for (int e = 0; e < 2; e++) {
            int li = tid + e * 256;
            int k4 = (li & 3) << 2;
            int mm = li >> 2;
            float4 f = *(const float4*)(A + (size_t)(m0 + mm) * D_ + k0 + k4);
            As[k4+0][mm] = f.x; As[k4+1][mm] = f.y; As[k4+2][mm] = f.z; As[k4+3][mm] = f.w;
            float4 g4 = *(const float4*)(Bk + (size_t)(n0 + mm) * D_ + k0 + k4);
            Bs[k4+0][mm] = g4.x; Bs[k4+1][mm] = g4.y; Bs[k4+2][mm] = g4.z; Bs[k4+3][mm] = g4.w;
        }
        __syncthreads();
        #pragma unroll
        for (int kk = 0; kk < 16; kk++) {
            float a[8], br[8];
            #pragma unroll
            for (int i = 0; i < 8; i++) a[i]  = As[kk][ty * 8 + i];
            #pragma unroll
            for (int j = 0; j < 8; j++) br[j] = Bs[kk][tx * 8 + j];
            #pragma unroll
            for (int i = 0; i < 8; i++)
                #pragma unroll
                for (int j = 0; j < 8; j++) acc[i][j] = fmaf(a[i], br[j], acc[i][j]);
        }
        __syncthreads();
    }

    const float* rd = g_rdot + (size_t)bn * L_ * 128;
    float* out = g_logits + (size_t)bn * L_ * L_;
    #pragma unroll
    for (int i = 0; i < 8; i++) {
        int ii = m0 + ty * 8 + i;
        int h = ii >> 5, w = ii & 31;
        const float* rrow = rd + (size_t)ii * 128;
        #pragma unroll
        for (int j = 0; j < 8; j++) {
            int jj = n0 + tx * 8 + j;
            int h2 = jj >> 5, w2 = jj & 31;
            float bias = rrow[w2 - w + 31] + rrow[63 + h2 - h + 31];
            out[(size_t)ii * L_ + jj] = acc[i][j] + bias;
        }
    }
}

// ---------------- softmax over rows of 1024 (in place) ----------------
__global__ void softmax_kernel() {
    const int row = blockIdx.x;
    float* p = g_logits + (size_t)row * L_;
    const int tid = threadIdx.x;
    float4 v4 = *(float4*)(p + tid * 4);
    float mx = fmaxf(fmaxf(v4.x, v4.y), fmaxf(v4.z, v4.w));
    __shared__ float smax[8], ssum[8];
    #pragma unroll
    for (int o = 16; o; o >>= 1) mx = fmaxf(mx, __shfl_xor_sync(~0u, mx, o));
    if ((tid & 31) == 0) smax[tid >> 5] = mx;
    __syncthreads();
    if (tid == 0) {
        float t = smax[0];
        #pragma unroll
        for (int i = 1; i < 8; i++) t = fmaxf(t, smax[i]);
        smax[0] = t;
    }
    __syncthreads();
    mx = smax[0];
    float e0 = __expf(v4.x - mx), e1 = __expf(v4.y - mx);
    float e2 = __expf(v4.z - mx), e3 = __expf(v4.w - mx);
    float s = (e0 + e1) + (e2 + e3);
    #pragma unroll
    for (int o = 16; o; o >>= 1) s += __shfl_xor_sync(~0u, s, o);
    if ((tid & 31) == 0) ssum[tid >> 5] = s;
    __syncthreads();
    if (tid == 0) {
        float t = 0.f;
        #pragma unroll
        for (int i = 0; i < 8; i++) t += ssum[i];
        ssum[0] = t;
    }
    __syncthreads();
    float inv = 1.0f / ssum[0];
    float4 r = make_float4(e0 * inv, e1 * inv, e2 * inv, e3 * inv);
    *(float4*)(p + tid * 4) = r;
}

// ---------------- AV GEMM + head merge + residual ----------------
__global__ __launch_bounds__(256) void av_kernel(const float* __restrict__ x) {
    __shared__ float As[16][128];
    __shared__ float Bs[16][128];
    const int bn = blockIdx.z;
    const int b = bn >> 2, nh = bn & 3;
    const int m0 = blockIdx.y * 128;
    const int tid = threadIdx.x;
    const int tx = tid & 15, ty = tid >> 4;
    const float* A  = g_logits + (size_t)bn * L_ * L_;
    const float* Bv = g_v      + (size_t)bn * L_ * D_;

    float acc[8][8];
    #pragma unroll
    for (int i = 0; i < 8; i++)
        #pragma unroll
        for (int j = 0; j < 8; j++) acc[i][j] = 0.f;

    for (int k0 = 0; k0 < L_; k0 += 16) {
        #pragma unroll
        for (int e = 0; e < 2; e++) {
            int li = tid + e * 256;
            int k4 = (li & 3) << 2;
            int mm = li >> 2;
            float4 f = *(const float4*)(A + (size_t)(m0 + mm) * L_ + k0 + k4);
            As[k4+0][mm] = f.x; As[k4+1][mm] = f.y; As[k4+2][mm] = f.z; As[k4+3][mm] = f.w;
        }
        #pragma unroll
        for (int e = 0; e < 2; e++) {
            int li = tid + e * 256;
            int nn = (li & 31) << 2;
            int kk = li >> 5;
            *(float4*)&Bs[kk][nn] = *(const float4*)(Bv + (size_t)(k0 + kk) * D_ + nn);
        }
        __syncthreads();
        #pragma unroll
        for (int kk = 0; kk < 16; kk++) {
            float a[8], br[8];
            #pragma unroll
            for (int i = 0; i < 8; i++) a[i]  = As[kk][ty * 8 + i];
            #pragma unroll
            for (int j = 0; j < 8; j++) br[j] = Bs[kk][tx * 8 + j];
            #pragma unroll
            for (int i = 0; i < 8; i++)
                #pragma unroll
                for (int j = 0; j < 8; j++) acc[i][j] = fmaf(a[i], br[j], acc[i][j]);
        }
        __syncthreads();
    }
    #pragma unroll
    for (int i = 0; i < 8; i++) {
        int ii = m0 + ty * 8 + i;
        #pragma unroll
        for (int j = 0; j < 8; j++) {
            int d = tx * 8 + j;
            size_t idx = (size_t)(b * C_ + nh * D_ + d) * L_ + ii;
            g_xres[idx] = acc[i][j] + x[idx];
        }
    }
}

// ---------------- weights -> bf16 hi/lo ----------------
__global__ void w2bf_kernel(const float* __restrict__ w) {
    int i = blockIdx.x * 256 + threadIdx.x;   // 512*4608 total
    float v = w[i];
    __nv_bfloat16 h = __float2bfloat16(v);
    g_w_hi[i] = h;
    g_w_lo[i] = __float2bfloat16(v - __bfloat162float(h));
}

// ---------------- im2col -> bf16 hi/lo, layout [b][l][k] ----------------
__global__ void im2col_bf_kernel() {
    int i = (blockIdx.x * 256 + threadIdx.x) * 2;    // element pairs, k fastest
    int k = i % KC_;
    int rest = i / KC_;
    int l = rest & (L_ - 1);
    int b = rest >> 10;
    int hh = l >> 5, ww = l & 31;
    __nv_bfloat16 hi[2], lo[2];
    #pragma unroll
    for (int u = 0; u < 2; ++u) {
        int kk = k + u;
        int c = kk / 9, r9 = kk % 9;
        int h = hh + r9 / 3 - 1, w = ww + r9 % 3 - 1;
        float val = 0.f;
        if ((unsigned)h < 32u && (unsigned)w < 32u)
            val = g_y2[((size_t)(b * C_ + c) << 10) + (h << 5) + w];
        hi[u] = __float2bfloat16(val);
        lo[u] = __float2bfloat16(val - __bfloat162float(hi[u]));
    }
    *(__nv_bfloat162*)(g_col_hi + i) = *(__nv_bfloat162*)hi;
    *(__nv_bfloat162*)(g_col_lo + i) = *(__nv_bfloat162*)lo;
}

// ---------------- conv GEMM via mma.sync bf16 (hi/lo split) ----------------
// D[o, l] = sum_k W[o,k] * col[l,k];  block tile M=128 (o) x N=128 (l), K-chunk 64.
// grid (8, 4, 8) = (l-tile, o-tile, batch). 256 threads = 8 warps (4 m x 2 n),
// warp tile 32(m) x 64(n). cp.async double buffer, SW128 swizzle, ldmatrix.x4.
#define NCHUNK 72
#define SUB_BYTES 16384              // one 128x64 bf16 subtile
#define BUF_BYTES (4 * SUB_BYTES)    // Ahi | Alo | Bhi | Blo
#define CONV_SMEM (1024 + 2 * BUF_BYTES)

__global__ __launch_bounds__(256, 1) void conv_mma_kernel(const float* __restrict__ bias_fc,
                                                          float* __restrict__ out) {
    extern __shared__ char smraw[];
    char* sm = (char*)(((uintptr_t)smraw + 1023) & ~(uintptr_t)1023);
    const uint32_t smb = smem_u32(sm);
    const int tid = threadIdx.x, wid = tid >> 5, lane = tid & 31;
    const int bb = blockIdx.z, m0 = blockIdx.y * 128, n0 = blockIdx.x * 128;

    const char* gAh = (const char*)g_w_hi  + (size_t)m0 * (KC_ * 2);
    const char* gAl = (const char*)g_w_lo  + (size_t)m0 * (KC_ * 2);
    const char* gBh = (const char*)g_col_hi + ((size_t)bb * L_ + n0) * (KC_ * 2);
    const char* gBl = (const char*)g_col_lo + ((size_t)bb * L_ + n0) * (KC_ * 2);

    // staging helper (4 segs per subtile per thread)
    auto stage = [&](int it, int buf) {
        const size_t koff = (size_t)it * 128;
        const uint32_t sb = smb + buf * BUF_BYTES;
        #pragma unroll
        for (int p = 0; p < 4; ++p) {
            int e = tid + (p << 8);
            int row = e >> 3;
            int sg = (e & 7) << 4;
            size_t g = (size_t)row * (KC_ * 2) + koff + sg;
            uint32_t s = SWZ((row << 7) + sg);
            cp16(sb + s,                 gAh + g);
            cp16(sb + SUB_BYTES + s,     gAl + g);
            cp16(sb + 2 * SUB_BYTES + s, gBh + g);
            cp16(sb + 3 * SUB_BYTES + s, gBl + g);
        }
    };

    float acc[2][8][4];
    #pragma unroll
    for (int i = 0; i < 2; i++)
        #pragma unroll
        for (int j = 0; j < 8; j++)
            #pragma unroll
            for (int t = 0; t < 4; t++) acc[i][j][t] = 0.f;

    const int wm = (wid & 3) << 5;      // warp m base (0,32,64,96)
    const int wn = (wid >> 2) << 6;     // warp n base (0,64)
    const int r  = lane & 15, hf = lane >> 4;

    stage(0, 0);
    CP_COMMIT();

    #pragma unroll 1
    for (int it = 0; it < NCHUNK; ++it) {
        const int buf = it & 1;
        if (it + 1 < NCHUNK) {
            stage(it + 1, buf ^ 1);
            CP_COMMIT();
            CP_WAIT(1);
        } else {
            CP_WAIT(0);
        }
        __syncthreads();

        const uint32_t sA  = smb + buf * BUF_BYTES;
        const uint32_t sAl = sA + SUB_BYTES;
        const uint32_t sB  = sA + 2 * SUB_BYTES;
        const uint32_t sBl = sA + 3 * SUB_BYTES;

        #pragma unroll
        for (int ks = 0; ks < 4; ++ks) {
            const int kb = ks << 5;     // byte offset of k16 step (16 bf16 = 32B)
            uint32_t ah[2][4], al[2][4];
            #pragma unroll
            for (int mt = 0; mt < 2; ++mt) {
                uint32_t rel = SWZ(((wm + (mt << 4) + r) << 7) + kb + (hf << 4));
                ldmx4(ah[mt], sA  + rel);
                ldmx4(al[mt], sAl + rel);
            }
            uint32_t bh[4][4], bl[4][4];
            #pragma unroll
            for (int np = 0; np < 4; ++np) {
                uint32_t rel = SWZ(((wn + (np << 4) + r) << 7) + kb + (hf << 4));
                ldmx4(bh[np], sB  + rel);
                ldmx4(bl[np], sBl + rel);
            }
            #pragma unroll
            for (int mt = 0; mt < 2; ++mt)
                #pragma unroll
                for (int np = 0; np < 4; ++np)
                    #pragma unroll
                    for (int sub = 0; sub < 2; ++sub) {
                        float* c = acc[mt][np * 2 + sub];
                        mma16816(c, ah[mt], bh[np][sub], bh[np][sub + 2]);
                        mma16816(c, ah[mt], bl[np][sub], bl[np][sub + 2]);
                        mma16816(c, al[mt], bh[np][sub], bh[np][sub + 2]);
                    }
        }
        __syncthreads();
    }

    // epilogue: bias + residual, write out
    const int lrow = lane >> 2;          // 0..7
    const int lcol = (lane & 3) << 1;    // 0,2,4,6
    #pragma unroll
    for (int mt = 0; mt < 2; ++mt) {
        #pragma unroll
        for (int nt = 0; nt < 8; ++nt) {
            const float* c = acc[mt][nt];
            int l = n0 + wn + (nt << 3) + lcol;
            #pragma unroll
            for (int half = 0; half < 2; ++half) {
                int o = m0 + wm + (mt << 4) + lrow + half * 8;
                float bv = bias_fc[o];
                size_t idx = ((size_t)(bb * C_ + o) << 10) + l;
                float2 xr = *(const float2*)(g_xres + idx);
                float2 o2;
                o2.x = c[half * 2 + 0] + bv + xr.x;
                o2.y = c[half * 2 + 1] + bv + xr.y;
                *(float2*)(out + idx) = o2;
            }
        }
    }
}

// ---------------- launch ----------------
extern "C" void kernel_launch(void* const* d_in, const int* in_sizes, int n_in,
                              void* d_out, int out_size) {
    const float* x       = (const float*)d_in[0];
    const float* w_qk    = (const float*)d_in[1];
    const float* w_v     = (const float*)d_in[2];
    const float* rel_h   = (const float*)d_in[3];
    const float* rel_w   = (const float*)d_in[4];
    const float* g1      = (const float*)d_in[5];
    const float* b1      = (const float*)d_in[6];
    const float* m1      = (const float*)d_in[7];
    const float* v1      = (const float*)d_in[8];
    const float* g2      = (const float*)d_in[9];
    const float* b2      = (const float*)d_in[10];
    const float* m2      = (const float*)d_in[11];
    const float* v2      = (const float*)d_in[12];
    const float* w_fc    = (const float*)d_in[13];
    const float* bias_fc = (const float*)d_in[14];
    float* out = (float*)d_out;

    cudaFuncSetAttribute(conv_mma_kernel, cudaFuncAttributeMaxDynamicSharedMemorySize, CONV_SMEM);

    bn_relu1_kernel<<<(B_*C_*L_)/256, 256>>>(x, g1, b1, m1, v1);
    proj_kernel<<<dim3(12, 8, B_), 256>>>(w_qk, w_v);
    relpos_kernel<<<B_*NH_*L_, 128>>>(rel_h, rel_w);
    logits_kernel<<<dim3(8, 8, B_*NH_), 256>>>();
    softmax_kernel<<<B_*NH_*L_, 256>>>();
    av_kernel<<<dim3(1, 8, B_*NH_), 256>>>(x);
    bn_relu2_kernel<<<(B_*C_*L_)/256, 256>>>(g2, b2, m2, v2);
    w2bf_kernel<<<(C_*KC_)/256, 256>>>(w_fc);
    im2col_bf_kernel<<<(B_*L_*KC_/2)/256, 256>>>();
    conv_mma_kernel<<<dim3(8, 4, B_), 256, CONV_SMEM>>>(bias_fc, out);
}

// round 4
// speedup vs baseline: 1.4001x; 1.1588x over previous
#include <cuda_runtime.h>
#include <cuda_bf16.h>
#include <cstdint>

// ---------------- problem constants ----------------
#define B_   8
#define C_   512
#define HH_  32
#define WW_  32
#define L_   1024          // HH*WW
#define NH_  4
#define D_   128
#define KC_  4608          // 512*9 (im2col K)
#define QSCALE 0.08838834764831845f  // 128^-0.5

// ---------------- scratch (device globals; no allocations) ----------------
__device__ __nv_bfloat16 g_xn_hi[B_*L_*C_];        // relu(bn1(x)) transposed [b][l][c]
__device__ __nv_bfloat16 g_xn_lo[B_*L_*C_];
__device__ __nv_bfloat16 g_wqkv_hi[1536*512];      // [o][c], o: q(0..511)|k|v
__device__ __nv_bfloat16 g_wqkv_lo[1536*512];
__device__ __nv_bfloat16 g_q_hi[32*L_*D_];         // [bn][l][d] (scaled)
__device__ __nv_bfloat16 g_q_lo[32*L_*D_];
__device__ __nv_bfloat16 g_k_hi[32*L_*D_];
__device__ __nv_bfloat16 g_k_lo[32*L_*D_];
__device__ __nv_bfloat16 g_v_hi[32*L_*D_];
__device__ __nv_bfloat16 g_v_lo[32*L_*D_];
__device__ float g_qf[32*L_*D_];                   // scaled q fp32 (for relpos)
__device__ float g_rdot[32*L_*128];                // rel dots (126 used)
__device__ float g_logits[(size_t)32*L_*L_];       // attn logits fp32
__device__ __nv_bfloat16 g_p_hi[(size_t)32*L_*L_]; // softmax probs hi/lo
__device__ __nv_bfloat16 g_p_lo[(size_t)32*L_*L_];
__device__ float g_xres[B_*C_*L_];                 // mhsa out + x
__device__ float g_y2[B_*C_*L_];                   // relu(bn2(xres))
__device__ __nv_bfloat16 g_w_hi[(size_t)C_*KC_];
__device__ __nv_bfloat16 g_w_lo[(size_t)C_*KC_];
__device__ __nv_bfloat16 g_col_hi[(size_t)B_*L_*KC_];  // [b][l][k]
__device__ __nv_bfloat16 g_col_lo[(size_t)B_*L_*KC_];

// ================= mma.sync helpers =================
__device__ __forceinline__ uint32_t smem_u32(const void* p) {
    uint32_t a;
    asm("{ .reg .u64 t; cvta.to.shared.u64 t, %1; cvt.u32.u64 %0, t; }" : "=r"(a) : "l"(p));
    return a;
}
__device__ __forceinline__ void cp16(uint32_t s, const void* g) {
    asm volatile("cp.async.cg.shared.global [%0], [%1], 16;" :: "r"(s), "l"(g));
}
#define CP_COMMIT() asm volatile("cp.async.commit_group;" ::: "memory")
#define CP_WAIT(n)  asm volatile("cp.async.wait_group %0;" :: "n"(n) : "memory")

__device__ __forceinline__ void ldmx4(uint32_t* d, uint32_t addr) {
    asm volatile("ldmatrix.sync.aligned.m8n8.x4.shared.b16 {%0,%1,%2,%3}, [%4];"
                 : "=r"(d[0]), "=r"(d[1]), "=r"(d[2]), "=r"(d[3]) : "r"(addr));
}
__device__ __forceinline__ void ldmx4t(uint32_t* d, uint32_t addr) {
    asm volatile("ldmatrix.sync.aligned.m8n8.x4.trans.shared.b16 {%0,%1,%2,%3}, [%4];"
                 : "=r"(d[0]), "=r"(d[1]), "=r"(d[2]), "=r"(d[3]) : "r"(addr));
}
__device__ __forceinline__ void mma16816(float* c, const uint32_t* a, uint32_t b0, uint32_t b1) {
    asm volatile("mma.sync.aligned.m16n8k16.row.col.f32.bf16.bf16.f32 "
                 "{%0,%1,%2,%3}, {%4,%5,%6,%7}, {%8,%9}, {%0,%1,%2,%3};"
                 : "+f"(c[0]), "+f"(c[1]), "+f"(c[2]), "+f"(c[3])
                 : "r"(a[0]), "r"(a[1]), "r"(a[2]), "r"(a[3]), "r"(b0), "r"(b1));
}
#define SWZ(x) ((x) ^ (((x) >> 3) & 0x70))

__device__ __forceinline__ void hilo(float v, __nv_bfloat16& h, __nv_bfloat16& l) {
    h = __float2bfloat16(v);
    l = __float2bfloat16(v - __bfloat162float(h));
}

// ---------------- BN1 + ReLU + transpose -> bf16 hi/lo [b][l][c] ----------------
__global__ void bn1t_kernel(const float* __restrict__ x,
                            const float* __restrict__ g, const float* __restrict__ bb,
                            const float* __restrict__ m, const float* __restrict__ v) {
    __shared__ float t[32][33];
    const int b = blockIdx.z, c0 = blockIdx.y * 32, l0 = blockIdx.x * 32;
    const int tid = threadIdx.x;
    {
        const int cr = tid >> 3, l4 = (tid & 7) * 4;
        const int c = c0 + cr;
        float inv = g[c] * rsqrtf(v[c] + 1e-5f);
        float sh  = bb[c] - m[c] * inv;
        float4 xv = *(const float4*)(x + ((size_t)(b * C_ + c) << 10) + l0 + l4);
        t[cr][l4 + 0] = fmaxf(fmaf(xv.x, inv, sh), 0.f);
        t[cr][l4 + 1] = fmaxf(fmaf(xv.y, inv, sh), 0.f);
        t[cr][l4 + 2] = fmaxf(fmaf(xv.z, inv, sh), 0.f);
        t[cr][l4 + 3] = fmaxf(fmaf(xv.w, inv, sh), 0.f);
    }
    __syncthreads();
    {
        const int lr = tid >> 3, c4 = (tid & 7) * 4;
        __nv_bfloat16 h[4], lo[4];
        #pragma unroll
        for (int u = 0; u < 4; ++u) hilo(t[c4 + u][lr], h[u], lo[u]);
        size_t base = ((size_t)(b * L_ + l0 + lr) << 9) + c0 + c4;
        *(__nv_bfloat162*)(g_xn_hi + base)     = *(__nv_bfloat162*)&h[0];
        *(__nv_bfloat162*)(g_xn_hi + base + 2) = *(__nv_bfloat162*)&h[2];
        *(__nv_bfloat162*)(g_xn_lo + base)     = *(__nv_bfloat162*)&lo[0];
        *(__nv_bfloat162*)(g_xn_lo + base + 2) = *(__nv_bfloat162*)&lo[2];
    }
}

// ---------------- BN2 + ReLU ----------------
__global__ void bn_relu2_kernel(const float* __restrict__ g, const float* __restrict__ bb,
                                const float* __restrict__ m, const float* __restrict__ v) {
    int idx = blockIdx.x * 256 + threadIdx.x;
    int c = (idx >> 10) & (C_ - 1);
    float inv = g[c] * rsqrtf(v[c] + 1e-5f);
    float val = fmaf(g_xres[idx], inv, bb[c] - m[c] * inv);
    g_y2[idx] = fmaxf(val, 0.0f);
}

// ---------------- qkv weights -> bf16 hi/lo ----------------
__global__ void wqkv2bf_kernel(const float* __restrict__ w_qk, const float* __restrict__ w_v) {
    int i = blockIdx.x * 256 + threadIdx.x;    // 1536*512
    float val = (i < 1024 * 512) ? w_qk[i] : w_v[i - 1024 * 512];
    hilo(val, g_wqkv_hi[i], g_wqkv_lo[i]);
}

// ---------------- conv weights -> bf16 hi/lo ----------------
__global__ void w2bf_kernel(const float* __restrict__ w) {
    int i = blockIdx.x * 256 + threadIdx.x;   // 512*4608
    hilo(w[i], g_w_hi[i], g_w_lo[i]);
}

// ---------------- QKV projection via mma.sync ----------------
// out[l, o] = sum_c xn[b][l][c] * wqkv[o][c];  M=1024(l), N=1536(o), K=512
// grid (12, 8, 8); tile 128x128, K-chunk 64, double buffer.
#define P_SUB 16384
#define P_BUF (4 * P_SUB)
#define PROJ_SMEM (1024 + 2 * P_BUF)
__global__ __launch_bounds__(256, 1) void proj_mma_kernel() {
    extern __shared__ char smraw[];
    char* sm = (char*)(((uintptr_t)smraw + 1023) & ~(uintptr_t)1023);
    const uint32_t smb = smem_u32(sm);
    const int tid = threadIdx.x, wid = tid >> 5, lane = tid & 31;
    const int b = blockIdx.z, m0 = blockIdx.y * 128, n0 = blockIdx.x * 128;

    const char* gAh = (const char*)g_xn_hi + (size_t)(b * L_ + m0) * 1024;
    const char* gAl = (const char*)g_xn_lo + (size_t)(b * L_ + m0) * 1024;
    const char* gBh = (const char*)g_wqkv_hi + (size_t)n0 * 1024;
    const char* gBl = (const char*)g_wqkv_lo + (size_t)n0 * 1024;

    auto stage = [&](int it, int buf) {
        const uint32_t sb = smb + buf * P_BUF;
        #pragma unroll
        for (int p = 0; p < 4; ++p) {
            int e = tid + (p << 8);
            int row = e >> 3;
            int sg = (e & 7) << 4;
            size_t go = (size_t)row * 1024 + (size_t)it * 128 + sg;
            uint32_t s = SWZ((row << 7) + sg);
            cp16(sb + s,             gAh + go);
            cp16(sb + P_SUB + s,     gAl + go);
            cp16(sb + 2 * P_SUB + s, gBh + go);
            cp16(sb + 3 * P_SUB + s, gBl + go);
        }
    };

    float acc[2][8][4];
    #pragma unroll
    for (int i = 0; i < 2; i++)
        #pragma unroll
        for (int j = 0; j < 8; j++)
            #pragma unroll
            for (int t = 0; t < 4; t++) acc[i][j][t] = 0.f;

    const int wm = (wid & 3) << 5, wn = (wid >> 2) << 6;
    const int r = lane & 15, hf = lane >> 4;

    stage(0, 0);
    CP_COMMIT();
    #pragma unroll 1
    for (int it = 0; it < 8; ++it) {
        const int buf = it & 1;
        if (it + 1 < 8) { stage(it + 1, buf ^ 1); CP_COMMIT(); CP_WAIT(1); }
        else CP_WAIT(0);
        __syncthreads();
        const uint32_t sA = smb + buf * P_BUF, sAl = sA + P_SUB;
        const uint32_t sB = sA + 2 * P_SUB, sBl = sA + 3 * P_SUB;
        #pragma unroll
        for (int ks = 0; ks < 4; ++ks) {
            const int kb = ks << 5;
            uint32_t ah[2][4], al[2][4];
            #pragma unroll
            for (int mt = 0; mt < 2; ++mt) {
                uint32_t rel = SWZ(((wm + (mt << 4) + r) << 7) + kb + (hf << 4));
                ldmx4(ah[mt], sA + rel);
                ldmx4(al[mt], sAl + rel);
            }
            uint32_t bh[4][4], bl[4][4];
            #pragma unroll
            for (int np = 0; np < 4; ++np) {
                uint32_t rel = SWZ(((wn + (np << 4) + r) << 7) + kb + (hf << 4));
                ldmx4(bh[np], sB + rel);
                ldmx4(bl[np], sBl + rel);
            }
            #pragma unroll
            for (int mt = 0; mt < 2; ++mt)
                #pragma unroll
                for (int np = 0; np < 4; ++np)
                    #pragma unroll
                    for (int sub = 0; sub < 2; ++sub) {
                        float* c = acc[mt][np * 2 + sub];
                        mma16816(c, ah[mt], bh[np][sub], bh[np][sub + 2]);
                        mma16816(c, ah[mt], bl[np][sub], bl[np][sub + 2]);
                        mma16816(c, al[mt], bh[np][sub], bh[np][sub + 2]);
                    }
        }
        __syncthreads();
    }

    // epilogue: route tile to q/k/v (whole tile is one tensor+head)
    const int region = n0 >> 9;                 // 0=q,1=k,2=v
    const int head = (n0 >> 7) & 3;
    const float scale = (region == 0) ? QSCALE : 1.0f;
    __nv_bfloat16 *dh, *dl;
    if (region == 0)      { dh = g_q_hi; dl = g_q_lo; }
    else if (region == 1) { dh = g_k_hi; dl = g_k_lo; }
    else                  { dh = g_v_hi; dl = g_v_lo; }
    const size_t bnbase = (size_t)(b * NH_ + head) * L_ * D_;
    const int lrow = lane >> 2, lcol = (lane & 3) << 1;
    #pragma unroll
    for (int mt = 0; mt < 2; ++mt) {
        #pragma unroll
        for (int nt = 0; nt < 8; ++nt) {
            const float* c = acc[mt][nt];
            const int d0 = wn + (nt << 3) + lcol;
            #pragma unroll
            for (int half = 0; half < 2; ++half) {
                int lv = m0 + wm + (mt << 4) + lrow + half * 8;
                float v0 = c[half * 2 + 0] * scale;
                float v1 = c[half * 2 + 1] * scale;
                size_t base = bnbase + ((size_t)lv << 7) + d0;
                __nv_bfloat16 h0, l0b, h1, l1b;
                hilo(v0, h0, l0b); hilo(v1, h1, l1b);
                __nv_bfloat162 hp; hp.x = h0; hp.y = h1;
                __nv_bfloat162 lp; lp.x = l0b; lp.y = l1b;
                *(__nv_bfloat162*)(dh + base) = hp;
                *(__nv_bfloat162*)(dl + base) = lp;
                if (region == 0) {
                    float2 f2; f2.x = v0; f2.y = v1;
                    *(float2*)(g_qf + base) = f2;
                }
            }
        }
    }
}

// ---------------- relative position dots ----------------
__global__ void relpos_kernel(const float* __restrict__ rel_h,
                              const float* __restrict__ rel_w) {
    __shared__ float qs[128];
    const int row = blockIdx.x;
    const int tid = threadIdx.x;
    qs[tid] = g_qf[(size_t)row * D_ + tid];
    __syncthreads();
    if (tid < 126) {
        const float* rk = (tid < 63) ? (rel_w + tid * D_) : (rel_h + (tid - 63) * D_);
        float s0 = 0.f, s1 = 0.f;
        #pragma unroll 16
        for (int d = 0; d < 128; d += 2) {
            s0 = fmaf(qs[d],     rk[d],     s0);
            s1 = fmaf(qs[d + 1], rk[d + 1], s1);
        }
        g_rdot[(size_t)row * 128 + tid] = s0 + s1;
    }
}

// ---------------- logits = Q Kᵀ + pos_bias via mma.sync ----------------
// K=128 single-shot. grid (8, 8, 32). 8 subtiles of 16KB:
// Ah0 Ah1 Al0 Al1 Bh0 Bh1 Bl0 Bl1 (d-halves 0:63 / 64:127)
#define LG_SUB 16384
#define LOG_SMEM (1024 + 8 * LG_SUB)
__global__ __launch_bounds__(256, 1) void logits_mma_kernel() {
    extern __shared__ char smraw[];
    char* sm = (char*)(((uintptr_t)smraw + 1023) & ~(uintptr_t)1023);
    const uint32_t smb = smem_u32(sm);
    const int tid = threadIdx.x, wid = tid >> 5, lane = tid & 31;
    const int bn = blockIdx.z, m0 = blockIdx.y * 128, n0 = blockIdx.x * 128;

    const char* gAh = (const char*)g_q_hi + (size_t)(bn * L_ + m0) * 256;
    const char* gAl = (const char*)g_q_lo + (size_t)(bn * L_ + m0) * 256;
    const char* gBh = (const char*)g_k_hi + (size_t)(bn * L_ + n0) * 256;
    const char* gBl = (const char*)g_k_lo + (size_t)(bn * L_ + n0) * 256;

    #pragma unroll
    for (int p = 0; p < 8; ++p) {
        int e = tid + (p << 8);
        int row = e >> 4;
        int sg = (e & 15) << 4;       // 0..240 within 256B row
        int half = sg >> 7;
        uint32_t s = SWZ((row << 7) + (sg & 127));
        size_t go = (size_t)row * 256 + sg;
        cp16(smb + half * LG_SUB + s,                gAh + go);
        cp16(smb + (2 + half) * LG_SUB + s,          gAl + go);
        cp16(smb + (4 + half) * LG_SUB + s,          gBh + go);
        cp16(smb + (6 + half) * LG_SUB + s,          gBl + go);
    }
    CP_COMMIT();

    float acc[2][8][4];
    #pragma unroll
    for (int i = 0; i < 2; i++)
        #pragma unroll
        for (int j = 0; j < 8; j++)
            #pragma unroll
            for (int t = 0; t < 4; t++) acc[i][j][t] = 0.f;

    const int wm = (wid & 3) << 5, wn = (wid >> 2) << 6;
    const int r = lane & 15, hf = lane >> 4;

    CP_WAIT(0);
    __syncthreads();

    #pragma unroll
    for (int ks = 0; ks < 8; ++ks) {
        const int kb = ks << 5;
        const int half = kb >> 7;
        const int ko = kb & 127;
        uint32_t ah[2][4], al[2][4];
        #pragma unroll
        for (int mt = 0; mt < 2; ++mt) {
            uint32_t rel = SWZ(((wm + (mt << 4) + r) << 7) + ko + (hf << 4));
            ldmx4(ah[mt], smb + half * LG_SUB + rel);
            ldmx4(al[mt], smb + (2 + half) * LG_SUB + rel);
        }
        uint32_t bh[4][4], bl[4][4];
        #pragma unroll
        for (int np = 0; np < 4; ++np) {
            uint32_t rel = SWZ(((wn + (np << 4) + r) << 7) + ko + (hf << 4));
            ldmx4(bh[np], smb + (4 + half) * LG_SUB + rel);
            ldmx4(bl[np], smb + (6 + half) * LG_SUB + rel);
        }
        #pragma unroll
        for (int mt = 0; mt < 2; ++mt)
            #pragma unroll
            for (int np = 0; np < 4; ++np)
                #pragma unroll
                for (int sub = 0; sub < 2; ++sub) {
                    float* c = acc[mt][np * 2 + sub];
                    mma16816(c, ah[mt], bh[np][sub], bh[np][sub + 2]);
                    mma16816(c, ah[mt], bl[np][sub], bl[np][sub + 2]);
                    mma16816(c, al[mt], bh[np][sub], bh[np][sub + 2]);
                }
    }

    const float* rd = g_rdot + (size_t)bn * L_ * 128;
    float* out = g_logits + (size_t)bn * L_ * L_;
    const int lrow = lane >> 2, lcol = (lane & 3) << 1;
    #pragma unroll
    for (int mt = 0; mt < 2; ++mt) {
        #pragma unroll
        for (int half = 0; half < 2; ++half) {
            const int ii = m0 + wm + (mt << 4) + lrow + half * 8;
            const int h = ii >> 5, w = ii & 31;
            const float* rrow = rd + (size_t)ii * 128;
            #pragma unroll
            for (int nt = 0; nt < 8; ++nt) {
                const float* c = acc[mt][nt];
                const int j0 = n0 + wn + (nt << 3) + lcol;
                #pragma unroll
                for (int u = 0; u < 2; ++u) {
                    int jj = j0 + u;
                    int h2 = jj >> 5, w2 = jj & 31;
                    float bias = rrow[w2 - w + 31] + rrow[63 + h2 - h + 31];
                    out[(size_t)ii * L_ + jj] = c[half * 2 + u] + bias;
                }
            }
        }
    }
}

// ---------------- softmax: fp32 logits -> bf16 hi/lo probs ----------------
__global__ void softmax_p_kernel() {
    const int row = blockIdx.x;
    const float* p = g_logits + (size_t)row * L_;
    const int tid = threadIdx.x;
    float4 v4 = *(const float4*)(p + tid * 4);
    float mx = fmaxf(fmaxf(v4.x, v4.y), fmaxf(v4.z, v4.w));
    __shared__ float smax[8], ssum[8];
    #pragma unroll
    for (int o = 16; o; o >>= 1) mx = fmaxf(mx, __shfl_xor_sync(~0u, mx, o));
    if ((tid & 31) == 0) smax[tid >> 5] = mx;
    __syncthreads();
    if (tid == 0) {
        float t = smax[0];
        #pragma unroll
        for (int i = 1; i < 8; i++) t = fmaxf(t, smax[i]);
        smax[0] = t;
    }
    __syncthreads();
    mx = smax[0];
    float e0 = __expf(v4.x - mx), e1 = __expf(v4.y - mx);
    float e2 = __expf(v4.z - mx), e3 = __expf(v4.w - mx);
    float s = (e0 + e1) + (e2 + e3);
    #pragma unroll
    for (int o = 16; o; o >>= 1) s += __shfl_xor_sync(~0u, s, o);
    if ((tid & 31) == 0) ssum[tid >> 5] = s;
    __syncthreads();
    if (tid == 0) {
        float t = 0.f;
        #pragma unroll
        for (int i = 0; i < 8; i++) t += ssum[i];
        ssum[0] = t;
    }
    __syncthreads();
    float inv = 1.0f / ssum[0];
    float pv[4] = { e0 * inv, e1 * inv, e2 * inv, e3 * inv };
    __nv_bfloat16 h[4], lo[4];
    #pragma unroll
    for (int u = 0; u < 4; ++u) hilo(pv[u], h[u], lo[u]);
    size_t base = (size_t)row * L_ + tid * 4;
    *(__nv_bfloat162*)(g_p_hi + base)     = *(__nv_bfloat162*)&h[0];
    *(__nv_bfloat162*)(g_p_hi + base + 2) = *(__nv_bfloat162*)&h[2];
    *(__nv_bfloat162*)(g_p_lo + base)     = *(__nv_bfloat162*)&lo[0];
    *(__nv_bfloat162*)(g_p_lo + base + 2) = *(__nv_bfloat162*)&lo[2];
}

// ---------------- AV via mma.sync (V via ldmatrix.trans) + residual ----------------
// out[i,d] = sum_j P[i][j] V[j][d];  M=1024(i), N=128(d), K=1024(j), chunk 64.
// grid (1, 8, 32). Buffers: Ah 16K | Al 16K | Bh 16K (2 d-half x 64 rows) | Bl 16K
#define AV_SUB 16384
#define AV_BUF (4 * AV_SUB)
#define AV_SMEM (1024 + 2 * AV_BUF)
__global__ __launch_bounds__(256, 1) void av_mma_kernel(const float* __restrict__ x) {
    extern __shared__ char smraw[];
    char* sm = (char*)(((uintptr_t)smraw + 1023) & ~(uintptr_t)1023);
    const uint32_t smb = smem_u32(sm);
    const int tid = threadIdx.x, wid = tid >> 5, lane = tid & 31;
    const int bn = blockIdx.z, m0 = blockIdx.y * 128;
    const int b = bn >> 2, head = bn & 3;

    const char* gAh = (const char*)g_p_hi + ((size_t)bn * L_ + m0) * 2048;
    const char* gAl = (const char*)g_p_lo + ((size_t)bn * L_ + m0) * 2048;
    const char* gBh = (const char*)g_v_hi + (size_t)bn * L_ * 256;
    const char* gBl = (const char*)g_v_lo + (size_t)bn * L_ * 256;

    auto stage = [&](int it, int buf) {
        const uint32_t sb = smb + buf * AV_BUF;
        #pragma unroll
        for (int p = 0; p < 4; ++p) {                 // A: 128 rows x 128B
            int e = tid + (p << 8);
            int row = e >> 3;
            int sg = (e & 7) << 4;
            size_t go = (size_t)row * 2048 + (size_t)it * 128 + sg;
            uint32_t s = SWZ((row << 7) + sg);
            cp16(sb + s,          gAh + go);
            cp16(sb + AV_SUB + s, gAl + go);
        }
        #pragma unroll
        for (int p = 0; p < 4; ++p) {                 // B: 64 j-rows x 256B, split by d-half
            int e = tid + (p << 8);
            int row = e >> 4;                          // 0..63
            int sg = (e & 15) << 4;                    // 0..240
            int half = sg >> 7;
            size_t go = ((size_t)(it * 64 + row)) * 256 + sg;
            uint32_t s = half * 8192 + SWZ((row << 7) + (sg & 127));
            cp16(sb + 2 * AV_SUB + s, gBh + go);
            cp16(sb + 3 * AV_SUB + s, gBl + go);
        }
    };

    float acc[2][8][4];
    #pragma unroll
    for (int i = 0; i < 2; i++)
        #pragma unroll
        for (int j = 0; j < 8; j++)
            #pragma unroll
            for (int t = 0; t < 4; t++) acc[i][j][t] = 0.f;

    const int wm = (wid & 3) << 5, wn = (wid >> 2) << 6;
    const int r = lane & 15, hf = lane >> 4;
    // trans ldmatrix lane mapping: jrow offset, d column
    const int tj = (lane & 7) + ((lane >> 4) << 3);   // k row: +8 for b1 matrices
    const int tn = ((lane >> 3) & 1) << 3;            // n: +8 for n-sub1

    stage(0, 0);
    CP_COMMIT();
    #pragma unroll 1
    for (int it = 0; it < 16; ++it) {
        const int buf = it & 1;
        if (it + 1 < 16) { stage(it + 1, buf ^ 1); CP_COMMIT(); CP_WAIT(1); }
        else CP_WAIT(0);
        __syncthreads();
        const uint32_t sA = smb + buf * AV_BUF, sAl = sA + AV_SUB;
        const uint32_t sB = sA + 2 * AV_SUB, sBl = sA + 3 * AV_SUB;
        #pragma unroll
        for (int ks = 0; ks < 4; ++ks) {
            const int kb = ks << 5;
            uint32_t ah[2][4], al[2][4];
            #pragma unroll
            for (int mt = 0; mt < 2; ++mt) {
                uint32_t rel = SWZ(((wm + (mt << 4) + r) << 7) + kb + (hf << 4));
                ldmx4(ah[mt], sA + rel);
                ldmx4(al[mt], sAl + rel);
            }
            uint32_t bh[4][4], bl[4][4];
            #pragma unroll
            for (int np = 0; np < 4; ++np) {
                const int jrow = ks * 16 + tj;
                const int dcol = wn + np * 16 + tn;
                const int db = dcol * 2;
                uint32_t rel = (uint32_t)((db >> 7) * 8192) + SWZ((jrow << 7) + (db & 127));
                ldmx4t(bh[np], sB + rel);
                ldmx4t(bl[np], sBl + rel);
            }
            #pragma unroll
            for (int mt = 0; mt < 2; ++mt)
                #pragma unroll
                for (int np = 0; np < 4; ++np)
                    #pragma unroll
                    for (int sub = 0; sub < 2; ++sub) {
                        float* c = acc[mt][np * 2 + sub];
                        mma16816(c, ah[mt], bh[np][sub], bh[np][sub + 2]);
                        mma16816(c, ah[mt], bl[np][sub], bl[np][sub + 2]);
                        mma16816(c, al[mt], bh[np][sub], bh[np][sub + 2]);
                    }
        }
        __syncthreads();
    }

    // epilogue: head merge + residual -> g_xres [b][c=head*128+d][i]
    const int lrow = lane >> 2, lcol = (lane & 3) << 1;
    #pragma unroll
    for (int mt = 0; mt < 2; ++mt) {
        #pragma unroll
        for (int nt = 0; nt < 8; ++nt) {
            const float* c = acc[mt][nt];
            const int d0 = wn + (nt << 3) + lcol;
            #pragma unroll
            for (int half = 0; half < 2; ++half) {
                int ii = m0 + wm + (mt << 4) + lrow + half * 8;
                #pragma unroll
                for (int u = 0; u < 2; ++u) {
                    size_t idx = ((size_t)(b * C_ + head * D_ + d0 + u) << 10) + ii;
                    g_xres[idx] = c[half * 2 + u] + x[idx];
                }
            }
        }
    }
}

// ---------------- im2col -> bf16 hi/lo, layout [b][l][k] ----------------
__global__ void im2col_bf_kernel() {
    int i = (blockIdx.x * 256 + threadIdx.x) * 2;
    int k = i % KC_;
    int rest = i / KC_;
    int l = rest & (L_ - 1);
    int b = rest >> 10;
    int hh = l >> 5, ww = l & 31;
    __nv_bfloat16 hi[2], lo[2];
    #pragma unroll
    for (int u = 0; u < 2; ++u) {
        int kk = k + u;
        int c = kk / 9, r9 = kk % 9;
        int h = hh + r9 / 3 - 1, w = ww + r9 % 3 - 1;
        float val = 0.f;
        if ((unsigned)h < 32u && (unsigned)w < 32u)
            val = g_y2[((size_t)(b * C_ + c) << 10) + (h << 5) + w];
        hilo(val, hi[u], lo[u]);
    }
    *(__nv_bfloat162*)(g_col_hi + i) = *(__nv_bfloat162*)hi;
    *(__nv_bfloat162*)(g_col_lo + i) = *(__nv_bfloat162*)lo;
}

// ---------------- conv GEMM via mma.sync bf16 (hi/lo) ----------------
#define NCHUNK 72
#define SUB_BYTES 16384
#define BUF_BYTES (4 * SUB_BYTES)
#define CONV_SMEM (1024 + 2 * BUF_BYTES)
__global__ __launch_bounds__(256, 1) void conv_mma_kernel(const float* __restrict__ bias_fc,
                                                          float* __restrict__ out) {
    extern __shared__ char smraw[];
    char* sm = (char*)(((uintptr_t)smraw + 1023) & ~(uintptr_t)1023);
    const uint32_t smb = smem_u32(sm);
    const int tid = threadIdx.x, wid = tid >> 5, lane = tid & 31;
    const int bb = blockIdx.z, m0 = blockIdx.y * 128, n0 = blockIdx.x * 128;

    const char* gAh = (const char*)g_w_hi  + (size_t)m0 * (KC_ * 2);
    const char* gAl = (const char*)g_w_lo  + (size_t)m0 * (KC_ * 2);
    const char* gBh = (const char*)g_col_hi + ((size_t)bb * L_ + n0) * (KC_ * 2);
    const char* gBl = (const char*)g_col_lo + ((size_t)bb * L_ + n0) * (KC_ * 2);

    auto stage = [&](int it, int buf) {
        const size_t koff = (size_t)it * 128;
        const uint32_t sb = smb + buf * BUF_BYTES;
        #pragma unroll
        for (int p = 0; p < 4; ++p) {
            int e = tid + (p << 8);
            int row = e >> 3;
            int sg = (e & 7) << 4;
            size_t g = (size_t)row * (KC_ * 2) + koff + sg;
            uint32_t s = SWZ((row << 7) + sg);
            cp16(sb + s,                 gAh + g);
            cp16(sb + SUB_BYTES + s,     gAl + g);
            cp16(sb + 2 * SUB_BYTES + s, gBh + g);
            cp16(sb + 3 * SUB_BYTES + s, gBl + g);
        }
    };

    float acc[2][8][4];
    #pragma unroll
    for (int i = 0; i < 2; i++)
        #pragma unroll
        for (int j = 0; j < 8; j++)
            #pragma unroll
            for (int t = 0; t < 4; t++) acc[i][j][t] = 0.f;

    const int wm = (wid & 3) << 5, wn = (wid >> 2) << 6;
    const int r = lane & 15, hf = lane >> 4;

    stage(0, 0);
    CP_COMMIT();
    #pragma unroll 1
    for (int it = 0; it < NCHUNK; ++it) {
        const int buf = it & 1;
        if (it + 1 < NCHUNK) { stage(it + 1, buf ^ 1); CP_COMMIT(); CP_WAIT(1); }
        else CP_WAIT(0);
        __syncthreads();
        const uint32_t sA = smb + buf * BUF_BYTES, sAl = sA + SUB_BYTES;
        const uint32_t sB = sA + 2 * SUB_BYTES, sBl = sA + 3 * SUB_BYTES;
        #pragma unroll
        for (int ks = 0; ks < 4; ++ks) {
            const int kb = ks << 5;
            uint32_t ah[2][4], al[2][4];
            #pragma unroll
            for (int mt = 0; mt < 2; ++mt) {
                uint32_t rel = SWZ(((wm + (mt << 4) + r) << 7) + kb + (hf << 4));
                ldmx4(ah[mt], sA + rel);
                ldmx4(al[mt], sAl + rel);
            }
            uint32_t bh[4][4], bl[4][4];
            #pragma unroll
            for (int np = 0; np < 4; ++np) {
                uint32_t rel = SWZ(((wn + (np << 4) + r) << 7) + kb + (hf << 4));
                ldmx4(bh[np], sB + rel);
                ldmx4(bl[np], sBl + rel);
            }
            #pragma unroll
            for (int mt = 0; mt < 2; ++mt)
                #pragma unroll
                for (int np = 0; np < 4; ++np)
                    #pragma unroll
                    for (int sub = 0; sub < 2; ++sub) {
                        float* c = acc[mt][np * 2 + sub];
                        mma16816(c, ah[mt], bh[np][sub], bh[np][sub + 2]);
                        mma16816(c, ah[mt], bl[np][sub], bl[np][sub + 2]);
                        mma16816(c, al[mt], bh[np][sub], bh[np][sub + 2]);
                    }
        }
        __syncthreads();
    }

    const int lrow = lane >> 2, lcol = (lane & 3) << 1;
    #pragma unroll
    for (int mt = 0; mt < 2; ++mt) {
        #pragma unroll
        for (int nt = 0; nt < 8; ++nt) {
            const float* c = acc[mt][nt];
            int l = n0 + wn + (nt << 3) + lcol;
            #pragma unroll
            for (int half = 0; half < 2; ++half) {
                int o = m0 + wm + (mt << 4) + lrow + half * 8;
                float bv = bias_fc[o];
                size_t idx = ((size_t)(bb * C_ + o) << 10) + l;
                float2 xr = *(const float2*)(g_xres + idx);
                float2 o2;
                o2.x = c[half * 2 + 0] + bv + xr.x;
                o2.y = c[half * 2 + 1] + bv + xr.y;
                *(float2*)(out + idx) = o2;
            }
        }
    }
}

// ---------------- launch ----------------
extern "C" void kernel_launch(void* const* d_in, const int* in_sizes, int n_in,
                              void* d_out, int out_size) {
    const float* x       = (const float*)d_in[0];
    const float* w_qk    = (const float*)d_in[1];
    const float* w_v     = (const float*)d_in[2];
    const float* rel_h   = (const float*)d_in[3];
    const float* rel_w   = (const float*)d_in[4];
    const float* g1      = (const float*)d_in[5];
    const float* b1      = (const float*)d_in[6];
    const float* m1      = (const float*)d_in[7];
    const float* v1      = (const float*)d_in[8];
    const float* g2      = (const float*)d_in[9];
    const float* b2      = (const float*)d_in[10];
    const float* m2      = (const float*)d_in[11];
    const float* v2      = (const float*)d_in[12];
    const float* w_fc    = (const float*)d_in[13];
    const float* bias_fc = (const float*)d_in[14];
    float* out = (float*)d_out;

    cudaFuncSetAttribute(proj_mma_kernel,   cudaFuncAttributeMaxDynamicSharedMemorySize, PROJ_SMEM);
    cudaFuncSetAttribute(logits_mma_kernel, cudaFuncAttributeMaxDynamicSharedMemorySize, LOG_SMEM);
    cudaFuncSetAttribute(av_mma_kernel,     cudaFuncAttributeMaxDynamicSharedMemorySize, AV_SMEM);
    cudaFuncSetAttribute(conv_mma_kernel,   cudaFuncAttributeMaxDynamicSharedMemorySize, CONV_SMEM);

    bn1t_kernel<<<dim3(32, 16, B_), 256>>>(x, g1, b1, m1, v1);
    wqkv2bf_kernel<<<(1536 * 512) / 256, 256>>>(w_qk, w_v);
    proj_mma_kernel<<<dim3(12, 8, B_), 256, PROJ_SMEM>>>();
    relpos_kernel<<<32 * L_, 128>>>(rel_h, rel_w);
    logits_mma_kernel<<<dim3(8, 8, 32), 256, LOG_SMEM>>>();
    softmax_p_kernel<<<32 * L_, 256>>>();
    av_mma_kernel<<<dim3(1, 8, 32), 256, AV_SMEM>>>(x);
    bn_relu2_kernel<<<(B_*C_*L_) / 256, 256>>>(g2, b2, m2, v2);
    w2bf_kernel<<<(C_*KC_) / 256, 256>>>(w_fc);
    im2col_bf_kernel<<<(B_*L_*KC_ / 2) / 256, 256>>>();
    conv_mma_kernel<<<dim3(8, 4, B_), 256, CONV_SMEM>>>(bias_fc, out);
}

// round 5
// speedup vs baseline: 1.5353x; 1.0965x over previous
#include <cuda_runtime.h>
#include <cuda_bf16.h>
#include <cstdint>

// ---------------- problem constants ----------------
#define B_   8
#define C_   512
#define HH_  32
#define WW_  32
#define L_   1024          // HH*WW
#define NH_  4
#define D_   128
#define KC_  4608          // 512*9 (im2col K)
#define QSCALE 0.08838834764831845f  // 128^-0.5

// ---------------- scratch (device globals; no allocations) ----------------
__device__ __nv_bfloat16 g_xn_hi[B_*L_*C_];        // relu(bn1(x)) transposed [b][l][c]
__device__ __nv_bfloat16 g_xn_lo[B_*L_*C_];
__device__ __nv_bfloat16 g_wqkv_hi[1536*512];      // [o][c], o: q|k|v
__device__ __nv_bfloat16 g_wqkv_lo[1536*512];
__device__ __nv_bfloat16 g_q_hi[32*L_*D_];         // [bn][l][d] (scaled)
__device__ __nv_bfloat16 g_q_lo[32*L_*D_];
__device__ __nv_bfloat16 g_k_hi[32*L_*D_];
__device__ __nv_bfloat16 g_k_lo[32*L_*D_];
__device__ __nv_bfloat16 g_v_hi[32*L_*D_];
__device__ __nv_bfloat16 g_v_lo[32*L_*D_];
__device__ float g_qf[32*L_*D_];                   // scaled q fp32 (for relpos)
__device__ float g_rdot[32*L_*128];                // rel dots (126 used)
__device__ float g_xres[B_*C_*L_];                 // mhsa out + x
__device__ __nv_bfloat16 g_y2t_hi[B_*L_*C_];       // relu(bn2(xres)) transposed [b][l][c]
__device__ __nv_bfloat16 g_y2t_lo[B_*L_*C_];
__device__ __nv_bfloat16 g_w_hi[(size_t)C_*KC_];   // reordered: [o][r9*512 + c]
__device__ __nv_bfloat16 g_w_lo[(size_t)C_*KC_];

// ================= mma.sync helpers =================
__device__ __forceinline__ uint32_t smem_u32(const void* p) {
    uint32_t a;
    asm("{ .reg .u64 t; cvta.to.shared.u64 t, %1; cvt.u32.u64 %0, t; }" : "=r"(a) : "l"(p));
    return a;
}
__device__ __forceinline__ void cp16(uint32_t s, const void* g) {
    asm volatile("cp.async.cg.shared.global [%0], [%1], 16;" :: "r"(s), "l"(g));
}
#define CP_COMMIT() asm volatile("cp.async.commit_group;" ::: "memory")
#define CP_WAIT(n)  asm volatile("cp.async.wait_group %0;" :: "n"(n) : "memory")

__device__ __forceinline__ void ldmx4(uint32_t* d, uint32_t addr) {
    asm volatile("ldmatrix.sync.aligned.m8n8.x4.shared.b16 {%0,%1,%2,%3}, [%4];"
                 : "=r"(d[0]), "=r"(d[1]), "=r"(d[2]), "=r"(d[3]) : "r"(addr));
}
__device__ __forceinline__ void ldmx4t(uint32_t* d, uint32_t addr) {
    asm volatile("ldmatrix.sync.aligned.m8n8.x4.trans.shared.b16 {%0,%1,%2,%3}, [%4];"
                 : "=r"(d[0]), "=r"(d[1]), "=r"(d[2]), "=r"(d[3]) : "r"(addr));
}
__device__ __forceinline__ void mma16816(float* c, const uint32_t* a, uint32_t b0, uint32_t b1) {
    asm volatile("mma.sync.aligned.m16n8k16.row.col.f32.bf16.bf16.f32 "
                 "{%0,%1,%2,%3}, {%4,%5,%6,%7}, {%8,%9}, {%0,%1,%2,%3};"
                 : "+f"(c[0]), "+f"(c[1]), "+f"(c[2]), "+f"(c[3])
                 : "r"(a[0]), "r"(a[1]), "r"(a[2]), "r"(a[3]), "r"(b0), "r"(b1));
}
#define SWZ(x) ((x) ^ (((x) >> 3) & 0x70))

__device__ __forceinline__ void hilo(float v, __nv_bfloat16& h, __nv_bfloat16& l) {
    h = __float2bfloat16(v);
    l = __float2bfloat16(v - __bfloat162float(h));
}
__device__ __forceinline__ uint32_t pack_hl(float a, float b, uint32_t& lo_out) {
    __nv_bfloat16 ah, al, bh, bl;
    hilo(a, ah, al); hilo(b, bh, bl);
    __nv_bfloat162 hp; hp.x = ah; hp.y = bh;
    __nv_bfloat162 lp; lp.x = al; lp.y = bl;
    lo_out = *(uint32_t*)&lp;
    return *(uint32_t*)&hp;
}

// ---------------- BN1 + ReLU + transpose -> bf16 hi/lo [b][l][c] ----------------
__global__ void bn1t_kernel(const float* __restrict__ x,
                            const float* __restrict__ g, const float* __restrict__ bb,
                            const float* __restrict__ m, const float* __restrict__ v) {
    __shared__ float t[32][33];
    const int b = blockIdx.z, c0 = blockIdx.y * 32, l0 = blockIdx.x * 32;
    const int tid = threadIdx.x;
    {
        const int cr = tid >> 3, l4 = (tid & 7) * 4;
        const int c = c0 + cr;
        float inv = g[c] * rsqrtf(v[c] + 1e-5f);
        float sh  = bb[c] - m[c] * inv;
        float4 xv = *(const float4*)(x + ((size_t)(b * C_ + c) << 10) + l0 + l4);
        t[cr][l4 + 0] = fmaxf(fmaf(xv.x, inv, sh), 0.f);
        t[cr][l4 + 1] = fmaxf(fmaf(xv.y, inv, sh), 0.f);
        t[cr][l4 + 2] = fmaxf(fmaf(xv.z, inv, sh), 0.f);
        t[cr][l4 + 3] = fmaxf(fmaf(xv.w, inv, sh), 0.f);
    }
    __syncthreads();
    {
        const int lr = tid >> 3, c4 = (tid & 7) * 4;
        __nv_bfloat16 h[4], lo[4];
        #pragma unroll
        for (int u = 0; u < 4; ++u) hilo(t[c4 + u][lr], h[u], lo[u]);
        size_t base = ((size_t)(b * L_ + l0 + lr) << 9) + c0 + c4;
        *(__nv_bfloat162*)(g_xn_hi + base)     = *(__nv_bfloat162*)&h[0];
        *(__nv_bfloat162*)(g_xn_hi + base + 2) = *(__nv_bfloat162*)&h[2];
        *(__nv_bfloat162*)(g_xn_lo + base)     = *(__nv_bfloat162*)&lo[0];
        *(__nv_bfloat162*)(g_xn_lo + base + 2) = *(__nv_bfloat162*)&lo[2];
    }
}

// ---------------- BN2 + ReLU + transpose -> bf16 hi/lo [b][l][c] ----------------
__global__ void bn2t_kernel(const float* __restrict__ g, const float* __restrict__ bb,
                            const float* __restrict__ m, const float* __restrict__ v) {
    __shared__ float t[32][33];
    const int b = blockIdx.z, c0 = blockIdx.y * 32, l0 = blockIdx.x * 32;
    const int tid = threadIdx.x;
    {
        const int cr = tid >> 3, l4 = (tid & 7) * 4;
        const int c = c0 + cr;
        float inv = g[c] * rsqrtf(v[c] + 1e-5f);
        float sh  = bb[c] - m[c] * inv;
        float4 xv = *(const float4*)(g_xres + ((size_t)(b * C_ + c) << 10) + l0 + l4);
        t[cr][l4 + 0] = fmaxf(fmaf(xv.x, inv, sh), 0.f);
        t[cr][l4 + 1] = fmaxf(fmaf(xv.y, inv, sh), 0.f);
        t[cr][l4 + 2] = fmaxf(fmaf(xv.z, inv, sh), 0.f);
        t[cr][l4 + 3] = fmaxf(fmaf(xv.w, inv, sh), 0.f);
    }
    __syncthreads();
    {
        const int lr = tid >> 3, c4 = (tid & 7) * 4;
        __nv_bfloat16 h[4], lo[4];
        #pragma unroll
        for (int u = 0; u < 4; ++u) hilo(t[c4 + u][lr], h[u], lo[u]);
        size_t base = ((size_t)(b * L_ + l0 + lr) << 9) + c0 + c4;
        *(__nv_bfloat162*)(g_y2t_hi + base)     = *(__nv_bfloat162*)&h[0];
        *(__nv_bfloat162*)(g_y2t_hi + base + 2) = *(__nv_bfloat162*)&h[2];
        *(__nv_bfloat162*)(g_y2t_lo + base)     = *(__nv_bfloat162*)&lo[0];
        *(__nv_bfloat162*)(g_y2t_lo + base + 2) = *(__nv_bfloat162*)&lo[2];
    }
}

// ---------------- qkv weights -> bf16 hi/lo ----------------
__global__ void wqkv2bf_kernel(const float* __restrict__ w_qk, const float* __restrict__ w_v) {
    int i = blockIdx.x * 256 + threadIdx.x;    // 1536*512
    float val = (i < 1024 * 512) ? w_qk[i] : w_v[i - 1024 * 512];
    hilo(val, g_wqkv_hi[i], g_wqkv_lo[i]);
}

// ---------------- conv weights -> bf16 hi/lo, reorder k' = r9*512 + c ----------------
__global__ void w2bf_kernel(const float* __restrict__ w) {
    int i = blockIdx.x * 256 + threadIdx.x;   // src: o*4608 + c*9 + r9
    int o = i / KC_, rem = i % KC_;
    int c = rem / 9, r9 = rem % 9;
    size_t dst = (size_t)o * KC_ + r9 * 512 + c;
    hilo(w[i], g_w_hi[dst], g_w_lo[dst]);
}

// ---------------- QKV projection via mma.sync ----------------
#define P_SUB 16384
#define P_BUF (4 * P_SUB)
#define PROJ_SMEM (1024 + 2 * P_BUF)
__global__ __launch_bounds__(256, 1) void proj_mma_kernel() {
    extern __shared__ char smraw[];
    char* sm = (char*)(((uintptr_t)smraw + 1023) & ~(uintptr_t)1023);
    const uint32_t smb = smem_u32(sm);
    const int tid = threadIdx.x, wid = tid >> 5, lane = tid & 31;
    const int b = blockIdx.z, m0 = blockIdx.y * 128, n0 = blockIdx.x * 128;

    const char* gAh = (const char*)g_xn_hi + (size_t)(b * L_ + m0) * 1024;
    const char* gAl = (const char*)g_xn_lo + (size_t)(b * L_ + m0) * 1024;
    const char* gBh = (const char*)g_wqkv_hi + (size_t)n0 * 1024;
    const char* gBl = (const char*)g_wqkv_lo + (size_t)n0 * 1024;

    auto stage = [&](int it, int buf) {
        const uint32_t sb = smb + buf * P_BUF;
        #pragma unroll
        for (int p = 0; p < 4; ++p) {
            int e = tid + (p << 8);
            int row = e >> 3;
            int sg = (e & 7) << 4;
            size_t go = (size_t)row * 1024 + (size_t)it * 128 + sg;
            uint32_t s = SWZ((row << 7) + sg);
            cp16(sb + s,             gAh + go);
            cp16(sb + P_SUB + s,     gAl + go);
            cp16(sb + 2 * P_SUB + s, gBh + go);
            cp16(sb + 3 * P_SUB + s, gBl + go);
        }
    };

    float acc[2][8][4];
    #pragma unroll
    for (int i = 0; i < 2; i++)
        #pragma unroll
        for (int j = 0; j < 8; j++)
            #pragma unroll
            for (int t = 0; t < 4; t++) acc[i][j][t] = 0.f;

    const int wm = (wid & 3) << 5, wn = (wid >> 2) << 6;
    const int r = lane & 15, hf = lane >> 4;

    stage(0, 0);
    CP_COMMIT();
    #pragma unroll 1
    for (int it = 0; it < 8; ++it) {
        const int buf = it & 1;
        if (it + 1 < 8) { stage(it + 1, buf ^ 1); CP_COMMIT(); CP_WAIT(1); }
        else CP_WAIT(0);
        __syncthreads();
        const uint32_t sA = smb + buf * P_BUF, sAl = sA + P_SUB;
        const uint32_t sB = sA + 2 * P_SUB, sBl = sA + 3 * P_SUB;
        #pragma unroll
        for (int ks = 0; ks < 4; ++ks) {
            const int kb = ks << 5;
            uint32_t ah[2][4], al[2][4];
            #pragma unroll
            for (int mt = 0; mt < 2; ++mt) {
                uint32_t rel = SWZ(((wm + (mt << 4) + r) << 7) + kb + (hf << 4));
                ldmx4(ah[mt], sA + rel);
                ldmx4(al[mt], sAl + rel);
            }
            uint32_t bh[4][4], bl[4][4];
            #pragma unroll
            for (int np = 0; np < 4; ++np) {
                uint32_t rel = SWZ(((wn + (np << 4) + r) << 7) + kb + (hf << 4));
                ldmx4(bh[np], sB + rel);
                ldmx4(bl[np], sBl + rel);
            }
            #pragma unroll
            for (int mt = 0; mt < 2; ++mt)
                #pragma unroll
                for (int np = 0; np < 4; ++np)
                    #pragma unroll
                    for (int sub = 0; sub < 2; ++sub) {
                        float* c = acc[mt][np * 2 + sub];
                        mma16816(c, ah[mt], bh[np][sub], bh[np][sub + 2]);
                        mma16816(c, ah[mt], bl[np][sub], bl[np][sub + 2]);
                        mma16816(c, al[mt], bh[np][sub], bh[np][sub + 2]);
                    }
        }
        __syncthreads();
    }

    const int region = n0 >> 9;                 // 0=q,1=k,2=v
    const int head = (n0 >> 7) & 3;
    const float scale = (region == 0) ? QSCALE : 1.0f;
    __nv_bfloat16 *dh, *dl;
    if (region == 0)      { dh = g_q_hi; dl = g_q_lo; }
    else if (region == 1) { dh = g_k_hi; dl = g_k_lo; }
    else                  { dh = g_v_hi; dl = g_v_lo; }
    const size_t bnbase = (size_t)(b * NH_ + head) * L_ * D_;
    const int lrow = lane >> 2, lcol = (lane & 3) << 1;
    #pragma unroll
    for (int mt = 0; mt < 2; ++mt) {
        #pragma unroll
        for (int nt = 0; nt < 8; ++nt) {
            const float* c = acc[mt][nt];
            const int d0 = wn + (nt << 3) + lcol;
            #pragma unroll
            for (int half = 0; half < 2; ++half) {
                int lv = m0 + wm + (mt << 4) + lrow + half * 8;
                float v0 = c[half * 2 + 0] * scale;
                float v1 = c[half * 2 + 1] * scale;
                size_t base = bnbase + ((size_t)lv << 7) + d0;
                uint32_t lo;
                uint32_t hi = pack_hl(v0, v1, lo);
                *(uint32_t*)(dh + base) = hi;
                *(uint32_t*)(dl + base) = lo;
                if (region == 0) {
                    float2 f2; f2.x = v0; f2.y = v1;
                    *(float2*)(g_qf + base) = f2;
                }
            }
        }
    }
}

// ---------------- relative position dots ----------------
__global__ void relpos_kernel(const float* __restrict__ rel_h,
                              const float* __restrict__ rel_w) {
    __shared__ float qs[128];
    const int row = blockIdx.x;
    const int tid = threadIdx.x;
    qs[tid] = g_qf[(size_t)row * D_ + tid];
    __syncthreads();
    if (tid < 126) {
        const float* rk = (tid < 63) ? (rel_w + tid * D_) : (rel_h + (tid - 63) * D_);
        float s0 = 0.f, s1 = 0.f;
        #pragma unroll 16
        for (int d = 0; d < 128; d += 2) {
            s0 = fmaf(qs[d],     rk[d],     s0);
            s1 = fmaf(qs[d + 1], rk[d + 1], s1);
        }
        g_rdot[(size_t)row * 128 + tid] = s0 + s1;
    }
}

// ---------------- fused flash attention + residual ----------------
// grid (8 m-tiles, 32 bn), 256 threads = 8 warps, each warp 16 rows x full width.
// smem: rdot 64KB | 2 stages x (Kh 16K | Kl 16K | Vh 16K | Vl 16K)
#define FA_STG0 65536
#define FA_STAGE 65536
#define FA_SMEM (1024 + FA_STG0 + 2 * FA_STAGE)
__global__ __launch_bounds__(256, 1) void flash_kernel(const float* __restrict__ x) {
    extern __shared__ char smraw[];
    char* sm = (char*)(((uintptr_t)smraw + 1023) & ~(uintptr_t)1023);
    const uint32_t smb = smem_u32(sm);
    const int tid = threadIdx.x, wid = tid >> 5, lane = tid & 31;
    const int m0 = blockIdx.x * 128, bn = blockIdx.y;
    const int b = bn >> 2, head = bn & 3;
    const int r = lane & 15, hf = lane >> 4;
    const int r2 = lane >> 2, lcol = (lane & 3) << 1;
    const int tj = (lane & 7) + ((lane >> 4) << 3);
    const int tn = ((lane >> 3) & 1) << 3;
    const int wm = wid << 4;

    // rdot rows -> smem [128][128] fp32
    {
        const char* src = (const char*)(g_rdot + ((size_t)bn * L_ + m0) * 128);
        #pragma unroll
        for (int p = 0; p < 16; ++p) {
            int e = tid + (p << 8);
            cp16(smb + e * 16, src + (size_t)e * 16);
        }
    }
    // Q -> smem staging area, then to regs (held for whole kernel)
    uint32_t qh[8][4], ql[8][4];
    {
        const char* gQh = (const char*)g_q_hi + ((size_t)bn * L_ + m0) * 256;
        const char* gQl = (const char*)g_q_lo + ((size_t)bn * L_ + m0) * 256;
        const uint32_t sb = smb + FA_STG0;
        #pragma unroll
        for (int p = 0; p < 8; ++p) {
            int e = tid + (p << 8);
            int row = e >> 4, sg = (e & 15) << 4;
            uint32_t s = ((sg >> 7) << 14) + SWZ((row << 7) + (sg & 127));
            size_t go = (size_t)row * 256 + sg;
            cp16(sb + s,         gQh + go);
            cp16(sb + 32768 + s, gQl + go);
        }
        CP_COMMIT(); CP_WAIT(0); __syncthreads();
        #pragma unroll
        for (int ks = 0; ks < 8; ++ks) {
            int ab = (ks << 5) + (hf << 4);
            uint32_t rel = ((ab >> 7) << 14) + SWZ(((wm + r) << 7) + (ab & 127));
            ldmx4(qh[ks], sb + rel);
            ldmx4(ql[ks], sb + 32768 + rel);
        }
        __syncthreads();
    }

    const char* gKh = (const char*)g_k_hi + (size_t)bn * L_ * 256;
    const char* gKl = (const char*)g_k_lo + (size_t)bn * L_ * 256;
    const char* gVh = (const char*)g_v_hi + (size_t)bn * L_ * 256;
    const char* gVl = (const char*)g_v_lo + (size_t)bn * L_ * 256;

    auto stageKV = [&](int jt, int buf) {
        const uint32_t sb = smb + FA_STG0 + buf * FA_STAGE;
        const size_t base = (size_t)(jt * 64) * 256;
        #pragma unroll
        for (int p = 0; p < 4; ++p) {
            int e = tid + (p << 8);
            int row = e >> 4, sg = (e & 15) << 4;
            uint32_t s = ((sg >> 7) << 13) + SWZ((row << 7) + (sg & 127));
            size_t go = base + (size_t)row * 256 + sg;
            cp16(sb + s,          gKh + go);
            cp16(sb + 16384 + s,  gKl + go);
            cp16(sb + 32768 + s,  gVh + go);
            cp16(sb + 49152 + s,  gVl + go);
        }
    };

    const int i0 = m0 + wm + r2, i1 = i0 + 8;
    const int h0 = i0 >> 5, w0 = i0 & 31;
    const int h1 = i1 >> 5, w1 = i1 & 31;
    const float* rd0 = (const float*)(sm + (size_t)(wm + r2) * 512);
    const float* rd1 = (const float*)(sm + (size_t)(wm + r2 + 8) * 512);

    float o[16][4];
    #pragma unroll
    for (int nt = 0; nt < 16; ++nt)
        #pragma unroll
        for (int u = 0; u < 4; ++u) o[nt][u] = 0.f;
    float m0r = -1e30f, m1r = -1e30f, s0r = 0.f, s1r = 0.f;

    stageKV(0, 0);
    CP_COMMIT();

    #pragma unroll 1
    for (int jt = 0; jt < 16; ++jt) {
        const int buf = jt & 1;
        if (jt + 1 < 16) { stageKV(jt + 1, buf ^ 1); CP_COMMIT(); CP_WAIT(1); }
        else CP_WAIT(0);
        __syncthreads();
        const uint32_t kb_s = smb + FA_STG0 + buf * FA_STAGE;

        // ---- S = Q K^T ----
        float s[8][4];
        #pragma unroll
        for (int t = 0; t < 8; ++t)
            #pragma unroll
            for (int u = 0; u < 4; ++u) s[t][u] = 0.f;
        #pragma unroll
        for (int ks = 0; ks < 8; ++ks) {
            int ab = (ks << 5) + (hf << 4);
            uint32_t bhf[4][4], blf[4][4];
            #pragma unroll
            for (int np = 0; np < 4; ++np) {
                uint32_t rel = ((ab >> 7) << 13) + SWZ((((np << 4) + r) << 7) + (ab & 127));
                ldmx4(bhf[np], kb_s + rel);
                ldmx4(blf[np], kb_s + 16384 + rel);
            }
            #pragma unroll
            for (int np = 0; np < 4; ++np)
                #pragma unroll
                for (int sub = 0; sub < 2; ++sub) {
                    float* c = s[np * 2 + sub];
                    mma16816(c, qh[ks], bhf[np][sub], bhf[np][sub + 2]);
                    mma16816(c, qh[ks], blf[np][sub], blf[np][sub + 2]);
                    mma16816(c, ql[ks], bhf[np][sub], bhf[np][sub + 2]);
                }
        }

        // ---- bias + row max ----
        const int j0 = jt * 64;
        float t0 = -1e30f, t1 = -1e30f;
        #pragma unroll
        for (int t = 0; t < 8; ++t) {
            int jj = j0 + t * 8 + lcol;
            int h2 = jj >> 5, w2 = jj & 31;
            float bh0 = rd0[94 + h2 - h0];
            float bh1 = rd1[94 + h2 - h1];
            s[t][0] += rd0[w2 - w0 + 31] + bh0;
            s[t][1] += rd0[w2 + 1 - w0 + 31] + bh0;
            s[t][2] += rd1[w2 - w1 + 31] + bh1;
            s[t][3] += rd1[w2 + 1 - w1 + 31] + bh1;
            t0 = fmaxf(t0, fmaxf(s[t][0], s[t][1]));
            t1 = fmaxf(t1, fmaxf(s[t][2], s[t][3]));
        }
        t0 = fmaxf(t0, __shfl_xor_sync(~0u, t0, 1));
        t0 = fmaxf(t0, __shfl_xor_sync(~0u, t0, 2));
        t1 = fmaxf(t1, __shfl_xor_sync(~0u, t1, 1));
        t1 = fmaxf(t1, __shfl_xor_sync(~0u, t1, 2));

        // ---- online softmax update ----
        float mn0 = fmaxf(m0r, t0), mn1 = fmaxf(m1r, t1);
        float a0 = __expf(m0r - mn0), a1 = __expf(m1r - mn1);
        #pragma unroll
        for (int nt = 0; nt < 16; ++nt) {
            o[nt][0] *= a0; o[nt][1] *= a0; o[nt][2] *= a1; o[nt][3] *= a1;
        }
        uint32_t ph[4][4], pl[4][4];
        float ts0 = 0.f, ts1 = 0.f;
        #pragma unroll
        for (int t = 0; t < 8; ++t) {
            float p0 = __expf(s[t][0] - mn0), p1 = __expf(s[t][1] - mn0);
            float p2 = __expf(s[t][2] - mn1), p3 = __expf(s[t][3] - mn1);
            ts0 += p0 + p1; ts1 += p2 + p3;
            int kt = t >> 1, wq = (t & 1) << 1;
            ph[kt][wq]     = pack_hl(p0, p1, pl[kt][wq]);
            ph[kt][wq + 1] = pack_hl(p2, p3, pl[kt][wq + 1]);
        }
        ts0 += __shfl_xor_sync(~0u, ts0, 1); ts0 += __shfl_xor_sync(~0u, ts0, 2);
        ts1 += __shfl_xor_sync(~0u, ts1, 1); ts1 += __shfl_xor_sync(~0u, ts1, 2);
        s0r = s0r * a0 + ts0; s1r = s1r * a1 + ts1;
        m0r = mn0; m1r = mn1;

        // ---- O += P V ----
        const uint32_t vb_s = kb_s + 32768;
        #pragma unroll
        for (int kt = 0; kt < 4; ++kt) {
            #pragma unroll
            for (int np = 0; np < 8; ++np) {
                int jrow = (kt << 4) + tj;
                int db = ((np << 4) + tn) << 1;
                uint32_t rel = ((db >> 7) << 13) + SWZ((jrow << 7) + (db & 127));
                uint32_t vh4[4], vl4[4];
                ldmx4t(vh4, vb_s + rel);
                ldmx4t(vl4, vb_s + 16384 + rel);
                #pragma unroll
                for (int sub = 0; sub < 2; ++sub) {
                    float* c = o[np * 2 + sub];
                    mma16816(c, ph[kt], vh4[sub], vh4[sub + 2]);
                    mma16816(c, ph[kt], vl4[sub], vl4[sub + 2]);
                    mma16816(c, pl[kt], vh4[sub], vh4[sub + 2]);
                }
            }
        }
        __syncthreads();
    }

    // ---- epilogue: normalize, head merge, residual ----
    float inv0 = 1.f / s0r, inv1 = 1.f / s1r;
    #pragma unroll
    for (int nt = 0; nt < 16; ++nt) {
        int d0 = (nt << 3) + lcol;
        #pragma unroll
        for (int u = 0; u < 2; ++u) {
            size_t ix0 = ((size_t)(b * C_ + head * D_ + d0 + u) << 10) + i0;
            size_t ix1 = ((size_t)(b * C_ + head * D_ + d0 + u) << 10) + i1;
            g_xres[ix0] = o[nt][u] * inv0 + x[ix0];
            g_xres[ix1] = o[nt][2 + u] * inv1 + x[ix1];
        }
    }
}

// ---------------- conv GEMM via mma.sync bf16 (hi/lo), implicit im2col ----------------
#define NCHUNK 72
#define SUB_BYTES 16384
#define BUF_BYTES (4 * SUB_BYTES)
#define CONV_SMEM (1024 + 2 * BUF_BYTES)
__global__ __launch_bounds__(256, 1) void conv_mma_kernel(const float* __restrict__ bias_fc,
                                                          float* __restrict__ out) {
    extern __shared__ char smraw[];
    char* sm = (char*)(((uintptr_t)smraw + 1023) & ~(uintptr_t)1023);
    const uint32_t smb = smem_u32(sm);
    const int tid = threadIdx.x, wid = tid >> 5, lane = tid & 31;
    const int bb = blockIdx.z, m0 = blockIdx.y * 128, n0 = blockIdx.x * 128;

    const char* gAh = (const char*)g_w_hi  + (size_t)m0 * (KC_ * 2);
    const char* gAl = (const char*)g_w_lo  + (size_t)m0 * (KC_ * 2);
    const char* yh  = (const char*)g_y2t_hi + (size_t)bb * L_ * 1024;
    const char* yl  = (const char*)g_y2t_lo + (size_t)bb * L_ * 1024;

    auto stage = [&](int it, int buf) {
        const size_t koff = (size_t)it * 128;
        const uint32_t sb = smb + buf * BUF_BYTES;
        #pragma unroll
        for (int p = 0; p < 4; ++p) {   // A: weights 128 rows x 128B
            int e = tid + (p << 8);
            int row = e >> 3;
            int sg = (e & 7) << 4;
            size_t g = (size_t)row * (KC_ * 2) + koff + sg;
            uint32_t s = SWZ((row << 7) + sg);
            cp16(sb + s,             gAh + g);
            cp16(sb + SUB_BYTES + s, gAl + g);
        }
        // B: implicit im2col — chunk it has uniform r9 (shift), c-range (it%8)*64
        const int r9 = it >> 3;
        const int dh = r9 / 3 - 1, dw = r9 % 3 - 1;
        const int cb2 = ((it & 7) << 6) * 2;      // byte offset of c0 in y2t row
        #pragma unroll
        for (int p = 0; p < 4; ++p) {
            int e = tid + (p << 8);
            int row = e >> 3;
            int sg = (e & 7) << 4;
            uint32_t s = SWZ((row << 7) + sg);
            int l = n0 + row;
            int h = (l >> 5) + dh, w = (l & 31) + dw;
            if ((unsigned)h < 32u && (unsigned)w < 32u) {
                size_t g = ((size_t)(l + dh * 32 + dw) << 10) + cb2 + sg;
                cp16(sb + 2 * SUB_BYTES + s, yh + g);
                cp16(sb + 3 * SUB_BYTES + s, yl + g);
            } else {
                uint4 z = make_uint4(0u, 0u, 0u, 0u);
                *(uint4*)(sm + ((size_t)buf * BUF_BYTES + 2 * SUB_BYTES + s)) = z;
                *(uint4*)(sm + ((size_t)buf * BUF_BYTES + 3 * SUB_BYTES + s)) = z;
            }
        }
    };

    float acc[2][8][4];
    #pragma unroll
    for (int i = 0; i < 2; i++)
        #pragma unroll
        for (int j = 0; j < 8; j++)
            #pragma unroll
            for (int t = 0; t < 4; t++) acc[i][j][t] = 0.f;

    const int wm = (wid & 3) << 5, wn = (wid >> 2) << 6;
    const int r = lane & 15, hf = lane >> 4;

    stage(0, 0);
    CP_COMMIT();
    #pragma unroll 1
    for (int it = 0; it < NCHUNK; ++it) {
        const int buf = it & 1;
        if (it + 1 < NCHUNK) { stage(it + 1, buf ^ 1); CP_COMMIT(); CP_WAIT(1); }
        else CP_WAIT(0);
        __syncthreads();
        const uint32_t sA = smb + buf * BUF_BYTES, sAl = sA + SUB_BYTES;
        const uint32_t sB = sA + 2 * SUB_BYTES, sBl = sA + 3 * SUB_BYTES;
        #pragma unroll
        for (int ks = 0; ks < 4; ++ks) {
            const int kb = ks << 5;
            uint32_t ah[2][4], al[2][4];
            #pragma unroll
            for (int mt = 0; mt < 2; ++mt) {
                uint32_t rel = SWZ(((wm + (mt << 4) + r) << 7) + kb + (hf << 4));
                ldmx4(ah[mt], sA + rel);
                ldmx4(al[mt], sAl + rel);
            }
            uint32_t bh[4][4], bl[4][4];
            #pragma unroll
            for (int np = 0; np < 4; ++np) {
                uint32_t rel = SWZ(((wn + (np << 4) + r) << 7) + kb + (hf << 4));
                ldmx4(bh[np], sB + rel);
                ldmx4(bl[np], sBl + rel);
            }
            #pragma unroll
            for (int mt = 0; mt < 2; ++mt)
                #pragma unroll
                for (int np = 0; np < 4; ++np)
                    #pragma unroll
                    for (int sub = 0; sub < 2; ++sub) {
                        float* c = acc[mt][np * 2 + sub];
                        mma16816(c, ah[mt], bh[np][sub], bh[np][sub + 2]);
                        mma16816(c, ah[mt], bl[np][sub], bl[np][sub + 2]);
                        mma16816(c, al[mt], bh[np][sub], bh[np][sub + 2]);
                    }
        }
        __syncthreads();
    }

    const int lrow = lane >> 2, lcol = (lane & 3) << 1;
    #pragma unroll
    for (int mt = 0; mt < 2; ++mt) {
        #pragma unroll
        for (int nt = 0; nt < 8; ++nt) {
            const float* c = acc[mt][nt];
            int l = n0 + wn + (nt << 3) + lcol;
            #pragma unroll
            for (int half = 0; half < 2; ++half) {
                int o = m0 + wm + (mt << 4) + lrow + half * 8;
                float bv = bias_fc[o];
                size_t idx = ((size_t)(bb * C_ + o) << 10) + l;
                float2 xr = *(const float2*)(g_xres + idx);
                float2 o2;
                o2.x = c[half * 2 + 0] + bv + xr.x;
                o2.y = c[half * 2 + 1] + bv + xr.y;
                *(float2*)(out + idx) = o2;
            }
        }
    }
}

// ---------------- launch ----------------
extern "C" void kernel_launch(void* const* d_in, const int* in_sizes, int n_in,
                              void* d_out, int out_size) {
    const float* x       = (const float*)d_in[0];
    const float* w_qk    = (const float*)d_in[1];
    const float* w_v     = (const float*)d_in[2];
    const float* rel_h   = (const float*)d_in[3];
    const float* rel_w   = (const float*)d_in[4];
    const float* g1      = (const float*)d_in[5];
    const float* b1      = (const float*)d_in[6];
    const float* m1      = (const float*)d_in[7];
    const float* v1      = (const float*)d_in[8];
    const float* g2      = (const float*)d_in[9];
    const float* b2      = (const float*)d_in[10];
    const float* m2      = (const float*)d_in[11];
    const float* v2      = (const float*)d_in[12];
    const float* w_fc    = (const float*)d_in[13];
    const float* bias_fc = (const float*)d_in[14];
    float* out = (float*)d_out;

    cudaFuncSetAttribute(proj_mma_kernel, cudaFuncAttributeMaxDynamicSharedMemorySize, PROJ_SMEM);
    cudaFuncSetAttribute(flash_kernel,    cudaFuncAttributeMaxDynamicSharedMemorySize, FA_SMEM);
    cudaFuncSetAttribute(conv_mma_kernel, cudaFuncAttributeMaxDynamicSharedMemorySize, CONV_SMEM);

    bn1t_kernel<<<dim3(32, 16, B_), 256>>>(x, g1, b1, m1, v1);
    wqkv2bf_kernel<<<(1536 * 512) / 256, 256>>>(w_qk, w_v);
    proj_mma_kernel<<<dim3(12, 8, B_), 256, PROJ_SMEM>>>();
    relpos_kernel<<<32 * L_, 128>>>(rel_h, rel_w);
    flash_kernel<<<dim3(8, 32), 256, FA_SMEM>>>(x);
    bn2t_kernel<<<dim3(32, 16, B_), 256>>>(g2, b2, m2, v2);
    w2bf_kernel<<<(C_ * KC_) / 256, 256>>>(w_fc);
    conv_mma_kernel<<<dim3(8, 4, B_), 256, CONV_SMEM>>>(bias_fc, out);
}

// round 6
// speedup vs baseline: 1.5531x; 1.0117x over previous
#include <cuda_runtime.h>
#include <cuda_bf16.h>
#include <cstdint>

// ---------------- problem constants ----------------
#define B_   8
#define C_   512
#define HH_  32
#define WW_  32
#define L_   1024          // HH*WW
#define NH_  4
#define D_   128
#define KC_  4608          // 512*9 (im2col K)
#define QSCALE 0.08838834764831845f  // 128^-0.5

// ---------------- scratch (device globals; no allocations) ----------------
__device__ __nv_bfloat16 g_xn_hi[B_*L_*C_];        // relu(bn1(x)) transposed [b][l][c]
__device__ __nv_bfloat16 g_xn_lo[B_*L_*C_];
__device__ __nv_bfloat16 g_wqkv_hi[1536*512];      // [o][c], o: q|k|v
__device__ __nv_bfloat16 g_wqkv_lo[1536*512];
__device__ __nv_bfloat16 g_q_hi[32*L_*D_];         // [bn][l][d] (scaled)
__device__ __nv_bfloat16 g_q_lo[32*L_*D_];
__device__ __nv_bfloat16 g_k_hi[32*L_*D_];
__device__ __nv_bfloat16 g_k_lo[32*L_*D_];
__device__ __nv_bfloat16 g_v_hi[32*L_*D_];
__device__ __nv_bfloat16 g_v_lo[32*L_*D_];
__device__ float g_qf[32*L_*D_];                   // scaled q fp32 (for relpos)
__device__ float g_rdot[32*L_*128];                // rel dots (126 used)
__device__ float g_xres[B_*C_*L_];                 // mhsa out + x
__device__ __nv_bfloat16 g_y2t_hi[B_*L_*C_];       // relu(bn2(xres)) transposed [b][l][c]
__device__ __nv_bfloat16 g_y2t_lo[B_*L_*C_];
__device__ __nv_bfloat16 g_w_hi[(size_t)C_*KC_];   // reordered: [o][r9*512 + c]
__device__ __nv_bfloat16 g_w_lo[(size_t)C_*KC_];

// ================= mma.sync helpers =================
__device__ __forceinline__ uint32_t smem_u32(const void* p) {
    uint32_t a;
    asm("{ .reg .u64 t; cvta.to.shared.u64 t, %1; cvt.u32.u64 %0, t; }" : "=r"(a) : "l"(p));
    return a;
}
__device__ __forceinline__ void cp16(uint32_t s, const void* g) {
    asm volatile("cp.async.cg.shared.global [%0], [%1], 16;" :: "r"(s), "l"(g));
}
#define CP_COMMIT() asm volatile("cp.async.commit_group;" ::: "memory")
#define CP_WAIT(n)  asm volatile("cp.async.wait_group %0;" :: "n"(n) : "memory")

__device__ __forceinline__ void ldmx4(uint32_t* d, uint32_t addr) {
    asm volatile("ldmatrix.sync.aligned.m8n8.x4.shared.b16 {%0,%1,%2,%3}, [%4];"
                 : "=r"(d[0]), "=r"(d[1]), "=r"(d[2]), "=r"(d[3]) : "r"(addr));
}
__device__ __forceinline__ void ldmx4t(uint32_t* d, uint32_t addr) {
    asm volatile("ldmatrix.sync.aligned.m8n8.x4.trans.shared.b16 {%0,%1,%2,%3}, [%4];"
                 : "=r"(d[0]), "=r"(d[1]), "=r"(d[2]), "=r"(d[3]) : "r"(addr));
}
__device__ __forceinline__ void mma16816(float* c, const uint32_t* a, uint32_t b0, uint32_t b1) {
    asm volatile("mma.sync.aligned.m16n8k16.row.col.f32.bf16.bf16.f32 "
                 "{%0,%1,%2,%3}, {%4,%5,%6,%7}, {%8,%9}, {%0,%1,%2,%3};"
                 : "+f"(c[0]), "+f"(c[1]), "+f"(c[2]), "+f"(c[3])
                 : "r"(a[0]), "r"(a[1]), "r"(a[2]), "r"(a[3]), "r"(b0), "r"(b1));
}
#define SWZ(x) ((x) ^ (((x) >> 3) & 0x70))

__device__ __forceinline__ void hilo(float v, __nv_bfloat16& h, __nv_bfloat16& l) {
    h = __float2bfloat16(v);
    l = __float2bfloat16(v - __bfloat162float(h));
}
__device__ __forceinline__ uint32_t pack_hl(float a, float b, uint32_t& lo_out) {
    __nv_bfloat16 ah, al, bh, bl;
    hilo(a, ah, al); hilo(b, bh, bl);
    __nv_bfloat162 hp; hp.x = ah; hp.y = bh;
    __nv_bfloat162 lp; lp.x = al; lp.y = bl;
    lo_out = *(uint32_t*)&lp;
    return *(uint32_t*)&hp;
}

// ---------------- BN1 + ReLU + transpose -> bf16 hi/lo [b][l][c] ----------------
__global__ void bn1t_kernel(const float* __restrict__ x,
                            const float* __restrict__ g, const float* __restrict__ bb,
                            const float* __restrict__ m, const float* __restrict__ v) {
    __shared__ float t[32][33];
    const int b = blockIdx.z, c0 = blockIdx.y * 32, l0 = blockIdx.x * 32;
    const int tid = threadIdx.x;
    {
        const int cr = tid >> 3, l4 = (tid & 7) * 4;
        const int c = c0 + cr;
        float inv = g[c] * rsqrtf(v[c] + 1e-5f);
        float sh  = bb[c] - m[c] * inv;
        float4 xv = *(const float4*)(x + ((size_t)(b * C_ + c) << 10) + l0 + l4);
        t[cr][l4 + 0] = fmaxf(fmaf(xv.x, inv, sh), 0.f);
        t[cr][l4 + 1] = fmaxf(fmaf(xv.y, inv, sh), 0.f);
        t[cr][l4 + 2] = fmaxf(fmaf(xv.z, inv, sh), 0.f);
        t[cr][l4 + 3] = fmaxf(fmaf(xv.w, inv, sh), 0.f);
    }
    __syncthreads();
    {
        const int lr = tid >> 3, c4 = (tid & 7) * 4;
        __nv_bfloat16 h[4], lo[4];
        #pragma unroll
        for (int u = 0; u < 4; ++u) hilo(t[c4 + u][lr], h[u], lo[u]);
        size_t base = ((size_t)(b * L_ + l0 + lr) << 9) + c0 + c4;
        *(__nv_bfloat162*)(g_xn_hi + base)     = *(__nv_bfloat162*)&h[0];
        *(__nv_bfloat162*)(g_xn_hi + base + 2) = *(__nv_bfloat162*)&h[2];
        *(__nv_bfloat162*)(g_xn_lo + base)     = *(__nv_bfloat162*)&lo[0];
        *(__nv_bfloat162*)(g_xn_lo + base + 2) = *(__nv_bfloat162*)&lo[2];
    }
}

// ---------------- BN2 + ReLU + transpose -> bf16 hi/lo [b][l][c] ----------------
__global__ void bn2t_kernel(const float* __restrict__ g, const float* __restrict__ bb,
                            const float* __restrict__ m, const float* __restrict__ v) {
    __shared__ float t[32][33];
    const int b = blockIdx.z, c0 = blockIdx.y * 32, l0 = blockIdx.x * 32;
    const int tid = threadIdx.x;
    {
        const int cr = tid >> 3, l4 = (tid & 7) * 4;
        const int c = c0 + cr;
        float inv = g[c] * rsqrtf(v[c] + 1e-5f);
        float sh  = bb[c] - m[c] * inv;
        float4 xv = *(const float4*)(g_xres + ((size_t)(b * C_ + c) << 10) + l0 + l4);
        t[cr][l4 + 0] = fmaxf(fmaf(xv.x, inv, sh), 0.f);
        t[cr][l4 + 1] = fmaxf(fmaf(xv.y, inv, sh), 0.f);
        t[cr][l4 + 2] = fmaxf(fmaf(xv.z, inv, sh), 0.f);
        t[cr][l4 + 3] = fmaxf(fmaf(xv.w, inv, sh), 0.f);
    }
    __syncthreads();
    {
        const int lr = tid >> 3, c4 = (tid & 7) * 4;
        __nv_bfloat16 h[4], lo[4];
        #pragma unroll
        for (int u = 0; u < 4; ++u) hilo(t[c4 + u][lr], h[u], lo[u]);
        size_t base = ((size_t)(b * L_ + l0 + lr) << 9) + c0 + c4;
        *(__nv_bfloat162*)(g_y2t_hi + base)     = *(__nv_bfloat162*)&h[0];
        *(__nv_bfloat162*)(g_y2t_hi + base + 2) = *(__nv_bfloat162*)&h[2];
        *(__nv_bfloat162*)(g_y2t_lo + base)     = *(__nv_bfloat162*)&lo[0];
        *(__nv_bfloat162*)(g_y2t_lo + base + 2) = *(__nv_bfloat162*)&lo[2];
    }
}

// ---------------- qkv weights -> bf16 hi/lo ----------------
__global__ void wqkv2bf_kernel(const float* __restrict__ w_qk, const float* __restrict__ w_v) {
    int i = blockIdx.x * 256 + threadIdx.x;    // 1536*512
    float val = (i < 1024 * 512) ? w_qk[i] : w_v[i - 1024 * 512];
    hilo(val, g_wqkv_hi[i], g_wqkv_lo[i]);
}

// ---------------- conv weights -> bf16 hi/lo, reorder k' = r9*512 + c ----------------
__global__ void w2bf_kernel(const float* __restrict__ w) {
    int i = blockIdx.x * 256 + threadIdx.x;   // src: o*4608 + c*9 + r9
    int o = i / KC_, rem = i % KC_;
    int c = rem / 9, r9 = rem % 9;
    size_t dst = (size_t)o * KC_ + r9 * 512 + c;
    hilo(w[i], g_w_hi[dst], g_w_lo[dst]);
}

// ---------------- QKV projection via mma.sync ----------------
#define P_SUB 16384
#define P_BUF (4 * P_SUB)
#define PROJ_SMEM (1024 + 2 * P_BUF)
__global__ __launch_bounds__(256, 1) void proj_mma_kernel() {
    extern __shared__ char smraw[];
    char* sm = (char*)(((uintptr_t)smraw + 1023) & ~(uintptr_t)1023);
    const uint32_t smb = smem_u32(sm);
    const int tid = threadIdx.x, wid = tid >> 5, lane = tid & 31;
    const int b = blockIdx.z, m0 = blockIdx.y * 128, n0 = blockIdx.x * 128;

    const char* gAh = (const char*)g_xn_hi + (size_t)(b * L_ + m0) * 1024;
    const char* gAl = (const char*)g_xn_lo + (size_t)(b * L_ + m0) * 1024;
    const char* gBh = (const char*)g_wqkv_hi + (size_t)n0 * 1024;
    const char* gBl = (const char*)g_wqkv_lo + (size_t)n0 * 1024;

    auto stage = [&](int it, int buf) {
        const uint32_t sb = smb + buf * P_BUF;
        #pragma unroll
        for (int p = 0; p < 4; ++p) {
            int e = tid + (p << 8);
            int row = e >> 3;
            int sg = (e & 7) << 4;
            size_t go = (size_t)row * 1024 + (size_t)it * 128 + sg;
            uint32_t s = SWZ((row << 7) + sg);
            cp16(sb + s,             gAh + go);
            cp16(sb + P_SUB + s,     gAl + go);
            cp16(sb + 2 * P_SUB + s, gBh + go);
            cp16(sb + 3 * P_SUB + s, gBl + go);
        }
    };

    float acc[2][8][4];
    #pragma unroll
    for (int i = 0; i < 2; i++)
        #pragma unroll
        for (int j = 0; j < 8; j++)
            #pragma unroll
            for (int t = 0; t < 4; t++) acc[i][j][t] = 0.f;

    const int wm = (wid & 3) << 5, wn = (wid >> 2) << 6;
    const int r = lane & 15, hf = lane >> 4;

    stage(0, 0);
    CP_COMMIT();
    #pragma unroll 1
    for (int it = 0; it < 8; ++it) {
        const int buf = it & 1;
        if (it + 1 < 8) { stage(it + 1, buf ^ 1); CP_COMMIT(); CP_WAIT(1); }
        else CP_WAIT(0);
        __syncthreads();
        const uint32_t sA = smb + buf * P_BUF, sAl = sA + P_SUB;
        const uint32_t sB = sA + 2 * P_SUB, sBl = sA + 3 * P_SUB;
        #pragma unroll
        for (int ks = 0; ks < 4; ++ks) {
            const int kb = ks << 5;
            uint32_t ah[2][4], al[2][4];
            #pragma unroll
            for (int mt = 0; mt < 2; ++mt) {
                uint32_t rel = SWZ(((wm + (mt << 4) + r) << 7) + kb + (hf << 4));
                ldmx4(ah[mt], sA + rel);
                ldmx4(al[mt], sAl + rel);
            }
            uint32_t bh[4][4], bl[4][4];
            #pragma unroll
            for (int np = 0; np < 4; ++np) {
                uint32_t rel = SWZ(((wn + (np << 4) + r) << 7) + kb + (hf << 4));
                ldmx4(bh[np], sB + rel);
                ldmx4(bl[np], sBl + rel);
            }
            #pragma unroll
            for (int mt = 0; mt < 2; ++mt)
                #pragma unroll
                for (int np = 0; np < 4; ++np)
                    #pragma unroll
                    for (int sub = 0; sub < 2; ++sub) {
                        float* c = acc[mt][np * 2 + sub];
                        mma16816(c, ah[mt], bh[np][sub], bh[np][sub + 2]);
                        mma16816(c, ah[mt], bl[np][sub], bl[np][sub + 2]);
                        mma16816(c, al[mt], bh[np][sub], bh[np][sub + 2]);
                    }
        }
        __syncthreads();
    }

    const int region = n0 >> 9;                 // 0=q,1=k,2=v
    const int head = (n0 >> 7) & 3;
    const float scale = (region == 0) ? QSCALE : 1.0f;
    __nv_bfloat16 *dh, *dl;
    if (region == 0)      { dh = g_q_hi; dl = g_q_lo; }
    else if (region == 1) { dh = g_k_hi; dl = g_k_lo; }
    else                  { dh = g_v_hi; dl = g_v_lo; }
    const size_t bnbase = (size_t)(b * NH_ + head) * L_ * D_;
    const int lrow = lane >> 2, lcol = (lane & 3) << 1;
    #pragma unroll
    for (int mt = 0; mt < 2; ++mt) {
        #pragma unroll
        for (int nt = 0; nt < 8; ++nt) {
            const float* c = acc[mt][nt];
            const int d0 = wn + (nt << 3) + lcol;
            #pragma unroll
            for (int half = 0; half < 2; ++half) {
                int lv = m0 + wm + (mt << 4) + lrow + half * 8;
                float v0 = c[half * 2 + 0] * scale;
                float v1 = c[half * 2 + 1] * scale;
                size_t base = bnbase + ((size_t)lv << 7) + d0;
                uint32_t lo;
                uint32_t hi = pack_hl(v0, v1, lo);
                *(uint32_t*)(dh + base) = hi;
                *(uint32_t*)(dl + base) = lo;
                if (region == 0) {
                    float2 f2; f2.x = v0; f2.y = v1;
                    *(float2*)(g_qf + base) = f2;
                }
            }
        }
    }
}

// ---------------- relative position dots ----------------
__global__ void relpos_kernel(const float* __restrict__ rel_h,
                              const float* __restrict__ rel_w) {
    __shared__ float qs[128];
    const int row = blockIdx.x;
    const int tid = threadIdx.x;
    qs[tid] = g_qf[(size_t)row * D_ + tid];
    __syncthreads();
    if (tid < 126) {
        const float* rk = (tid < 63) ? (rel_w + tid * D_) : (rel_h + (tid - 63) * D_);
        float s0 = 0.f, s1 = 0.f;
        #pragma unroll 16
        for (int d = 0; d < 128; d += 2) {
            s0 = fmaf(qs[d],     rk[d],     s0);
            s1 = fmaf(qs[d + 1], rk[d + 1], s1);
        }
        g_rdot[(size_t)row * 128 + tid] = s0 + s1;
    }
}

// ---------------- fused flash attention + residual ----------------
// grid (8 m-tiles, 32 bn), 256 threads = 8 warps, each warp 16 rows x full width.
// smem: rdot 64KB | 2 stages x (Kh 16K | Kl 16K | Vh 16K | Vl 16K)
#define FA_STG0 65536
#define FA_STAGE 65536
#define FA_SMEM (1024 + FA_STG0 + 2 * FA_STAGE)
__global__ __launch_bounds__(256, 1) void flash_kernel(const float* __restrict__ x) {
    extern __shared__ char smraw[];
    char* sm = (char*)(((uintptr_t)smraw + 1023) & ~(uintptr_t)1023);
    const uint32_t smb = smem_u32(sm);
    const int tid = threadIdx.x, wid = tid >> 5, lane = tid & 31;
    const int m0 = blockIdx.x * 128, bn = blockIdx.y;
    const int b = bn >> 2, head = bn & 3;
    const int r = lane & 15, hf = lane >> 4;
    const int r2 = lane >> 2, lcol = (lane & 3) << 1;
    const int tj = (lane & 7) + ((lane >> 4) << 3);
    const int tn = ((lane >> 3) & 1) << 3;
    const int wm = wid << 4;

    // rdot rows -> smem [128][128] fp32
    {
        const char* src = (const char*)(g_rdot + ((size_t)bn * L_ + m0) * 128);
        #pragma unroll
        for (int p = 0; p < 16; ++p) {
            int e = tid + (p << 8);
            cp16(smb + e * 16, src + (size_t)e * 16);
        }
    }
    // Q -> smem staging area, then to regs (held for whole kernel)
    uint32_t qh[8][4], ql[8][4];
    {
        const char* gQh = (const char*)g_q_hi + ((size_t)bn * L_ + m0) * 256;
        const char* gQl = (const char*)g_q_lo + ((size_t)bn * L_ + m0) * 256;
        const uint32_t sb = smb + FA_STG0;
        #pragma unroll
        for (int p = 0; p < 8; ++p) {
            int e = tid + (p << 8);
            int row = e >> 4, sg = (e & 15) << 4;
            uint32_t s = ((sg >> 7) << 14) + SWZ((row << 7) + (sg & 127));
            size_t go = (size_t)row * 256 + sg;
            cp16(sb + s,         gQh + go);
            cp16(sb + 32768 + s, gQl + go);
        }
        CP_COMMIT(); CP_WAIT(0); __syncthreads();
        #pragma unroll
        for (int ks = 0; ks < 8; ++ks) {
            int ab = (ks << 5) + (hf << 4);
            uint32_t rel = ((ab >> 7) << 14) + SWZ(((wm + r) << 7) + (ab & 127));
            ldmx4(qh[ks], sb + rel);
            ldmx4(ql[ks], sb + 32768 + rel);
        }
        __syncthreads();
    }

    const char* gKh = (const char*)g_k_hi + (size_t)bn * L_ * 256;
    const char* gKl = (const char*)g_k_lo + (size_t)bn * L_ * 256;
    const char* gVh = (const char*)g_v_hi + (size_t)bn * L_ * 256;
    const char* gVl = (const char*)g_v_lo + (size_t)bn * L_ * 256;

    auto stageKV = [&](int jt, int buf) {
        const uint32_t sb = smb + FA_STG0 + buf * FA_STAGE;
        const size_t base = (size_t)(jt * 64) * 256;
        #pragma unroll
        for (int p = 0; p < 4; ++p) {
            int e = tid + (p << 8);
            int row = e >> 4, sg = (e & 15) << 4;
            uint32_t s = ((sg >> 7) << 13) + SWZ((row << 7) + (sg & 127));
            size_t go = base + (size_t)row * 256 + sg;
            cp16(sb + s,          gKh + go);
            cp16(sb + 16384 + s,  gKl + go);
            cp16(sb + 32768 + s,  gVh + go);
            cp16(sb + 49152 + s,  gVl + go);
        }
    };

    const int i0 = m0 + wm + r2, i1 = i0 + 8;
    const int h0 = i0 >> 5, w0 = i0 & 31;
    const int h1 = i1 >> 5, w1 = i1 & 31;
    const float* rd0 = (const float*)(sm + (size_t)(wm + r2) * 512);
    const float* rd1 = (const float*)(sm + (size_t)(wm + r2 + 8) * 512);

    float o[16][4];
    #pragma unroll
    for (int nt = 0; nt < 16; ++nt)
        #pragma unroll
        for (int u = 0; u < 4; ++u) o[nt][u] = 0.f;
    float m0r = -1e30f, m1r = -1e30f, s0r = 0.f, s1r = 0.f;

    stageKV(0, 0);
    CP_COMMIT();

    #pragma unroll 1
    for (int jt = 0; jt < 16; ++jt) {
        const int buf = jt & 1;
        if (jt + 1 < 16) { stageKV(jt + 1, buf ^ 1); CP_COMMIT(); CP_WAIT(1); }
        else CP_WAIT(0);
        __syncthreads();
        const uint32_t kb_s = smb + FA_STG0 + buf * FA_STAGE;

        // ---- S = Q K^T ----
        float s[8][4];
        #pragma unroll
        for (int t = 0; t < 8; ++t)
            #pragma unroll
            for (int u = 0; u < 4; ++u) s[t][u] = 0.f;
        #pragma unroll
        for (int ks = 0; ks < 8; ++ks) {
            int ab = (ks << 5) + (hf << 4);
            uint32_t bhf[4][4], blf[4][4];
            #pragma unroll
            for (int np = 0; np < 4; ++np) {
                uint32_t rel = ((ab >> 7) << 13) + SWZ((((np << 4) + r) << 7) + (ab & 127));
                ldmx4(bhf[np], kb_s + rel);
                ldmx4(blf[np], kb_s + 16384 + rel);
            }
            #pragma unroll
            for (int np = 0; np < 4; ++np)
                #pragma unroll
                for (int sub = 0; sub < 2; ++sub) {
                    float* c = s[np * 2 + sub];
                    mma16816(c, qh[ks], bhf[np][sub], bhf[np][sub + 2]);
                    mma16816(c, qh[ks], blf[np][sub], blf[np][sub + 2]);
                    mma16816(c, ql[ks], bhf[np][sub], bhf[np][sub + 2]);
                }
        }

        // ---- bias + row max ----
        const int j0 = jt * 64;
        float t0 = -1e30f, t1 = -1e30f;
        #pragma unroll
        for (int t = 0; t < 8; ++t) {
            int jj = j0 + t * 8 + lcol;
            int h2 = jj >> 5, w2 = jj & 31;
            float bh0 = rd0[94 + h2 - h0];
            float bh1 = rd1[94 + h2 - h1];
            s[t][0] += rd0[w2 - w0 + 31] + bh0;
            s[t][1] += rd0[w2 + 1 - w0 + 31] + bh0;
            s[t][2] += rd1[w2 - w1 + 31] + bh1;
            s[t][3] += rd1[w2 + 1 - w1 + 31] + bh1;
            t0 = fmaxf(t0, fmaxf(s[t][0], s[t][1]));
            t1 = fmaxf(t1, fmaxf(s[t][2], s[t][3]));
        }
        t0 = fmaxf(t0, __shfl_xor_sync(~0u, t0, 1));
        t0 = fmaxf(t0, __shfl_xor_sync(~0u, t0, 2));
        t1 = fmaxf(t1, __shfl_xor_sync(~0u, t1, 1));
        t1 = fmaxf(t1, __shfl_xor_sync(~0u, t1, 2));

        // ---- online softmax update ----
        float mn0 = fmaxf(m0r, t0), mn1 = fmaxf(m1r, t1);
        float a0 = __expf(m0r - mn0), a1 = __expf(m1r - mn1);
        #pragma unroll
        for (int nt = 0; nt < 16; ++nt) {
            o[nt][0] *= a0; o[nt][1] *= a0; o[nt][2] *= a1; o[nt][3] *= a1;
        }
        uint32_t ph[4][4], pl[4][4];
        float ts0 = 0.f, ts1 = 0.f;
        #pragma unroll
        for (int t = 0; t < 8; ++t) {
            float p0 = __expf(s[t][0] - mn0), p1 = __expf(s[t][1] - mn0);
            float p2 = __expf(s[t][2] - mn1), p3 = __expf(s[t][3] - mn1);
            ts0 += p0 + p1; ts1 += p2 + p3;
            int kt = t >> 1, wq = (t & 1) << 1;
            ph[kt][wq]     = pack_hl(p0, p1, pl[kt][wq]);
            ph[kt][wq + 1] = pack_hl(p2, p3, pl[kt][wq + 1]);
        }
        ts0 += __shfl_xor_sync(~0u, ts0, 1); ts0 += __shfl_xor_sync(~0u, ts0, 2);
        ts1 += __shfl_xor_sync(~0u, ts1, 1); ts1 += __shfl_xor_sync(~0u, ts1, 2);
        s0r = s0r * a0 + ts0; s1r = s1r * a1 + ts1;
        m0r = mn0; m1r = mn1;

        // ---- O += P V ----
        const uint32_t vb_s = kb_s + 32768;
        #pragma unroll
        for (int kt = 0; kt < 4; ++kt) {
            #pragma unroll
            for (int np = 0; np < 8; ++np) {
                int jrow = (kt << 4) + tj;
                int db = ((np << 4) + tn) << 1;
                uint32_t rel = ((db >> 7) << 13) + SWZ((jrow << 7) + (db & 127));
                uint32_t vh4[4], vl4[4];
                ldmx4t(vh4, vb_s + rel);
                ldmx4t(vl4, vb_s + 16384 + rel);
                #pragma unroll
                for (int sub = 0; sub < 2; ++sub) {
                    float* c = o[np * 2 + sub];
                    mma16816(c, ph[kt], vh4[sub], vh4[sub + 2]);
                    mma16816(c, ph[kt], vl4[sub], vl4[sub + 2]);
                    mma16816(c, pl[kt], vh4[sub], vh4[sub + 2]);
                }
            }
        }
        __syncthreads();
    }

    // ---- epilogue: normalize -> smem transpose -> coalesced residual+store ----
    __syncthreads();
    float* so = (float*)sm;                 // [128 d][136 stride] fp32
    const float inv0 = 1.f / s0r, inv1 = 1.f / s1r;
    #pragma unroll
    for (int nt = 0; nt < 16; ++nt) {
        const int d0 = (nt << 3) + lcol;
        #pragma unroll
        for (int u = 0; u < 2; ++u) {
            so[(d0 + u) * 136 + wm + r2]     = o[nt][u] * inv0;
            so[(d0 + u) * 136 + wm + r2 + 8] = o[nt][2 + u] * inv1;
        }
    }
    __syncthreads();
    #pragma unroll
    for (int ch = 0; ch < 16; ++ch) {
        const int d = (ch << 3) + (tid >> 5);
        const int i4 = (tid & 31) << 2;
        const size_t idx = ((size_t)(b * C_ + head * D_ + d) << 10) + m0 + i4;
        float4 xr = *(const float4*)(x + idx);
        float4 ov = *(const float4*)(so + d * 136 + i4);
        ov.x += xr.x; ov.y += xr.y; ov.z += xr.z; ov.w += xr.w;
        *(float4*)(g_xres + idx) = ov;
    }
}

// ---------------- conv GEMM via mma.sync bf16 (hi/lo), implicit im2col ----------------
// tile M=128 (o) x N=256 (l); grid (4,4,8) = 128 CTAs = one full wave.
#define NCHUNK 72
#define CV_SUBA 16384
#define CV_SUBB 32768
#define CV_BUF (2 * CV_SUBA + 2 * CV_SUBB)   // Ah | Al | Bh | Bl = 96KB
#define CONV_SMEM (1024 + 2 * CV_BUF)
__global__ __launch_bounds__(256, 1) void conv_mma_kernel(const float* __restrict__ bias_fc,
                                                          float* __restrict__ out) {
    extern __shared__ char smraw[];
    char* sm = (char*)(((uintptr_t)smraw + 1023) & ~(uintptr_t)1023);
    const uint32_t smb = smem_u32(sm);
    const int tid = threadIdx.x, wid = tid >> 5, lane = tid & 31;
    const int bb = blockIdx.z, m0 = blockIdx.y * 128, n0 = blockIdx.x * 256;

    const char* gAh = (const char*)g_w_hi  + (size_t)m0 * (KC_ * 2);
    const char* gAl = (const char*)g_w_lo  + (size_t)m0 * (KC_ * 2);
    const char* yh  = (const char*)g_y2t_hi + (size_t)bb * L_ * 1024;
    const char* yl  = (const char*)g_y2t_lo + (size_t)bb * L_ * 1024;

    auto stage = [&](int it, int buf) {
        const size_t koff = (size_t)it * 128;
        const uint32_t sb = smb + buf * CV_BUF;
        #pragma unroll
        for (int p = 0; p < 4; ++p) {   // A: weights 128 rows x 128B
            int e = tid + (p << 8);
            int row = e >> 3;
            int sg = (e & 7) << 4;
            size_t g = (size_t)row * (KC_ * 2) + koff + sg;
            uint32_t s = SWZ((row << 7) + sg);
            cp16(sb + s,           gAh + g);
            cp16(sb + CV_SUBA + s, gAl + g);
        }
        // B: implicit im2col — chunk it has uniform r9 (shift), c-range (it%8)*64
        const int r9 = it >> 3;
        const int dh = r9 / 3 - 1, dw = r9 % 3 - 1;
        const int cb2 = ((it & 7) << 6) * 2;      // byte offset of c0 in y2t row
        #pragma unroll
        for (int p = 0; p < 8; ++p) {             // 256 rows x 128B
            int e = tid + (p << 8);
            int row = e >> 3;
            int sg = (e & 7) << 4;
            uint32_t s = SWZ((row << 7) + sg);
            int l = n0 + row;
            int h = (l >> 5) + dh, w = (l & 31) + dw;
            if ((unsigned)h < 32u && (unsigned)w < 32u) {
                size_t g = ((size_t)(l + dh * 32 + dw) << 10) + cb2 + sg;
                cp16(sb + 2 * CV_SUBA + s,           yh + g);
                cp16(sb + 2 * CV_SUBA + CV_SUBB + s, yl + g);
            } else {
                uint4 z = make_uint4(0u, 0u, 0u, 0u);
                *(uint4*)(sm + ((size_t)buf * CV_BUF + 2 * CV_SUBA + s)) = z;
                *(uint4*)(sm + ((size_t)buf * CV_BUF + 2 * CV_SUBA + CV_SUBB + s)) = z;
            }
        }
    };

    float acc[2][16][4];
    #pragma unroll
    for (int i = 0; i < 2; i++)
        #pragma unroll
        for (int j = 0; j < 16; j++)
            #pragma unroll
            for (int t = 0; t < 4; t++) acc[i][j][t] = 0.f;

    const int wm = (wid & 3) << 5, wn = (wid >> 2) << 7;   // warp tile 32m x 128n
    const int r = lane & 15, hf = lane >> 4;

    stage(0, 0);
    CP_COMMIT();
    #pragma unroll 1
    for (int it = 0; it < NCHUNK; ++it) {
        const int buf = it & 1;
        if (it + 1 < NCHUNK) { stage(it + 1, buf ^ 1); CP_COMMIT(); CP_WAIT(1); }
        else CP_WAIT(0);
        __syncthreads();
        const uint32_t sA = smb + buf * CV_BUF, sAl = sA + CV_SUBA;
        const uint32_t sB = sA + 2 * CV_SUBA, sBl = sB + CV_SUBB;
        #pragma unroll
        for (int ks = 0; ks < 4; ++ks) {
            const int kb = ks << 5;
            uint32_t ah[2][4], al[2][4];
            #pragma unroll
            for (int mt = 0; mt < 2; ++mt) {
                uint32_t rel = SWZ(((wm + (mt << 4) + r) << 7) + kb + (hf << 4));
                ldmx4(ah[mt], sA + rel);
                ldmx4(al[mt], sAl + rel);
            }
            #pragma unroll
            for (int np = 0; np < 8; ++np) {
                uint32_t rel = SWZ(((wn + (np << 4) + r) << 7) + kb + (hf << 4));
                uint32_t bh[4], bl[4];
                ldmx4(bh, sB + rel);
                ldmx4(bl, sBl + rel);
                #pragma unroll
                for (int mt = 0; mt < 2; ++mt)
                    #pragma unroll
                    for (int sub = 0; sub < 2; ++sub) {
                        float* c = acc[mt][np * 2 + sub];
                        mma16816(c, ah[mt], bh[sub], bh[sub + 2]);
                        mma16816(c, ah[mt], bl[sub], bl[sub + 2]);
                        mma16816(c, al[mt], bh[sub], bh[sub + 2]);
                    }
            }
        }
        __syncthreads();
    }

    const int lrow = lane >> 2, lcol = (lane & 3) << 1;
    #pragma unroll
    for (int mt = 0; mt < 2; ++mt) {
        #pragma unroll
        for (int nt = 0; nt < 16; ++nt) {
            const float* c = acc[mt][nt];
            int l = n0 + wn + (nt << 3) + lcol;
            #pragma unroll
            for (int half = 0; half < 2; ++half) {
                int o = m0 + wm + (mt << 4) + lrow + half * 8;
                float bv = bias_fc[o];
                size_t idx = ((size_t)(bb * C_ + o) << 10) + l;
                float2 xr = *(const float2*)(g_xres + idx);
                float2 o2;
                o2.x = c[half * 2 + 0] + bv + xr.x;
                o2.y = c[half * 2 + 1] + bv + xr.y;
                *(float2*)(out + idx) = o2;
            }
        }
    }
}

// ---------------- launch ----------------
extern "C" void kernel_launch(void* const* d_in, const int* in_sizes, int n_in,
                              void* d_out, int out_size) {
    const float* x       = (const float*)d_in[0];
    const float* w_qk    = (const float*)d_in[1];
    const float* w_v     = (const float*)d_in[2];
    const float* rel_h   = (const float*)d_in[3];
    const float* rel_w   = (const float*)d_in[4];
    const float* g1      = (const float*)d_in[5];
    const float* b1      = (const float*)d_in[6];
    const float* m1      = (const float*)d_in[7];
    const float* v1      = (const float*)d_in[8];
    const float* g2      = (const float*)d_in[9];
    const float* b2      = (const float*)d_in[10];
    const float* m2      = (const float*)d_in[11];
    const float* v2      = (const float*)d_in[12];
    const float* w_fc    = (const float*)d_in[13];
    const float* bias_fc = (const float*)d_in[14];
    float* out = (float*)d_out;

    cudaFuncSetAttribute(proj_mma_kernel, cudaFuncAttributeMaxDynamicSharedMemorySize, PROJ_SMEM);
    cudaFuncSetAttribute(flash_kernel,    cudaFuncAttributeMaxDynamicSharedMemorySize, FA_SMEM);
    cudaFuncSetAttribute(conv_mma_kernel, cudaFuncAttributeMaxDynamicSharedMemorySize, CONV_SMEM);

    bn1t_kernel<<<dim3(32, 16, B_), 256>>>(x, g1, b1, m1, v1);
    wqkv2bf_kernel<<<(1536 * 512) / 256, 256>>>(w_qk, w_v);
    proj_mma_kernel<<<dim3(12, 8, B_), 256, PROJ_SMEM>>>();
    relpos_kernel<<<32 * L_, 128>>>(rel_h, rel_w);
    flash_kernel<<<dim3(8, 32), 256, FA_SMEM>>>(x);
    bn2t_kernel<<<dim3(32, 16, B_), 256>>>(g2, b2, m2, v2);
    w2bf_kernel<<<(C_ * KC_) / 256, 256>>>(w_fc);
    conv_mma_kernel<<<dim3(4, 4, B_), 256, CONV_SMEM>>>(bias_fc, out);
}